// round 1
// baseline (speedup 1.0000x reference)
#include <cuda_runtime.h>
#include <math.h>

#define D     1024
#define NH    16
#define HD    64
#define FF    4096
#define SEQ   2048
#define BATCH 2
#define MTOK  (BATCH*SEQ)   // 4096 rows

// ---------------- scratch (static device globals; no allocs) ----------------
__device__ float g_q[MTOK*(size_t)D];
__device__ float g_k[MTOK*(size_t)D];
__device__ float g_v[MTOK*(size_t)D];
__device__ float g_ctx[MTOK*(size_t)D];
__device__ float g_attn[MTOK*(size_t)D];
__device__ float g_h[MTOK*(size_t)D];
__device__ float g_ff1[MTOK*(size_t)FF];
__device__ float g_ff2[MTOK*(size_t)D];

// ---------------- SGEMM: C[M,N] = A[M,K] @ B[K,N] + bias, optional GELU -----
// BM=BN=128, BK=16, 256 threads, 8x8 per thread.
template <int EPI>  // 0 = none, 1 = exact erf-GELU
__global__ __launch_bounds__(256) void sgemm_bias(
    const float* __restrict__ A, const float* __restrict__ Bm,
    const float* __restrict__ bias, float* __restrict__ C,
    int M, int N, int K)
{
    const int BM = 128, BN = 128, BK = 16;
    __shared__ float As[BK][BM];   // transposed A tile
    __shared__ float Bs[BK][BN];

    const int tid = threadIdx.x;
    const int tx = tid & 15;        // 0..15 -> N
    const int ty = tid >> 4;        // 0..15 -> M
    const int bx = blockIdx.x;      // N tile
    const int by = blockIdx.y;      // M tile

    const float* Aptr = A + (size_t)by * BM * K;
    const float* Bptr = Bm + (size_t)bx * BN;

    float acc[8][8];
    #pragma unroll
    for (int i = 0; i < 8; i++)
        #pragma unroll
        for (int j = 0; j < 8; j++) acc[i][j] = 0.f;

    for (int kt = 0; kt < K; kt += BK) {
        // load A tile: 128x16 floats = 512 float4; 2 per thread; store transposed
        #pragma unroll
        for (int l = 0; l < 2; l++) {
            int f = tid + l * 256;
            int row = f >> 2;        // 0..127
            int c4  = f & 3;         // 0..3
            float4 va = *(const float4*)(Aptr + (size_t)row * K + kt + c4 * 4);
            As[c4*4+0][row] = va.x;
            As[c4*4+1][row] = va.y;
            As[c4*4+2][row] = va.z;
            As[c4*4+3][row] = va.w;
        }
        // load B tile: 16x128 floats = 512 float4; 2 per thread
        #pragma unroll
        for (int l = 0; l < 2; l++) {
            int f = tid + l * 256;
            int row = f >> 5;        // 0..15
            int c4  = f & 31;        // 0..31
            float4 vb = *(const float4*)(Bptr + (size_t)(kt + row) * N + c4 * 4);
            *(float4*)(&Bs[row][c4*4]) = vb;
        }
        __syncthreads();

        #pragma unroll
        for (int kk = 0; kk < BK; kk++) {
            float a[8], b[8];
            *(float4*)(a)     = *(const float4*)(&As[kk][ty*8]);
            *(float4*)(a + 4) = *(const float4*)(&As[kk][ty*8 + 4]);
            *(float4*)(b)     = *(const float4*)(&Bs[kk][tx*8]);
            *(float4*)(b + 4) = *(const float4*)(&Bs[kk][tx*8 + 4]);
            #pragma unroll
            for (int i = 0; i < 8; i++)
                #pragma unroll
                for (int j = 0; j < 8; j++)
                    acc[i][j] = fmaf(a[i], b[j], acc[i][j]);
        }
        __syncthreads();
    }

    // epilogue
    #pragma unroll
    for (int i = 0; i < 8; i++) {
        int r = by * BM + ty * 8 + i;
        float* crow = C + (size_t)r * N + bx * BN + tx * 8;
        #pragma unroll
        for (int j = 0; j < 8; j++) {
            float v = acc[i][j] + bias[bx * BN + tx * 8 + j];
            if (EPI == 1) v = 0.5f * v * (1.f + erff(v * 0.70710678118654752f));
            crow[j] = v;
        }
    }
}

// ---------------- causal flash attention --------------------------------
// q,k,v laid out [b, s, h, hd] contiguous as [MTOK, D].
// grid: (SEQ/128, NH, BATCH), block: 128 threads; 1 thread = 1 query row.
__global__ __launch_bounds__(128) void attn_kernel(
    const float* __restrict__ q, const float* __restrict__ k,
    const float* __restrict__ v, float* __restrict__ ctx)
{
    __shared__ float Ks[64][HD];
    __shared__ float Vs[64][HD];

    const int tid = threadIdx.x;
    const int qi  = blockIdx.x * 128 + tid;   // seq position of this thread's query
    const int h   = blockIdx.y;
    const int b   = blockIdx.z;
    const float scale = 0.125f;               // 1/sqrt(64)

    float qr[HD];
    const float* qp = q + ((size_t)(b * SEQ + qi)) * D + h * HD;
    #pragma unroll
    for (int d = 0; d < HD; d++) qr[d] = qp[d] * scale;

    float m = -1e30f, l = 0.f;
    float acc[HD];
    #pragma unroll
    for (int d = 0; d < HD; d++) acc[d] = 0.f;

    const int ktiles = blockIdx.x * 2 + 2;    // 64-key tiles covering keys <= q_end

    for (int kt = 0; kt < ktiles; kt++) {
        __syncthreads();
        const float* kbase = k + ((size_t)(b * SEQ + kt * 64)) * D + h * HD;
        const float* vbase = v + ((size_t)(b * SEQ + kt * 64)) * D + h * HD;
        // 64*64 floats per tensor = 1024 float4 each; 128 threads -> 8 iters
        for (int f = tid; f < 64 * (HD / 4); f += 128) {
            int row = f >> 4;          // /(HD/4)=16
            int c4  = f & 15;
            *(float4*)(&Ks[row][c4*4]) = *(const float4*)(kbase + (size_t)row * D + c4 * 4);
            *(float4*)(&Vs[row][c4*4]) = *(const float4*)(vbase + (size_t)row * D + c4 * 4);
        }
        __syncthreads();

        int kmax = qi - kt * 64 + 1;
        if (kmax > 64) kmax = 64;
        for (int kk = 0; kk < kmax; kk++) {
            float s = 0.f;
            #pragma unroll
            for (int d = 0; d < HD; d++) s = fmaf(qr[d], Ks[kk][d], s);
            if (s > m) {
                float c = __expf(m - s);
                l *= c;
                #pragma unroll
                for (int d = 0; d < HD; d++) acc[d] *= c;
                m = s;
            }
            float p = __expf(s - m);
            l += p;
            #pragma unroll
            for (int d = 0; d < HD; d++) acc[d] = fmaf(p, Vs[kk][d], acc[d]);
        }
    }

    float inv = 1.f / l;
    float* op = ctx + ((size_t)(b * SEQ + qi)) * D + h * HD;
    #pragma unroll
    for (int d = 0; d < HD; d++) op[d] = acc[d] * inv;
}

// ---------------- fused residual add + LayerNorm ------------------------
// out[row] = LN(Ain[row] + Bin[row]) * g + beta.  One block per row, 256 thr.
__global__ __launch_bounds__(256) void add_ln(
    const float* __restrict__ Ain, const float* __restrict__ Bin,
    const float* __restrict__ g, const float* __restrict__ be,
    float* __restrict__ out)
{
    const int row = blockIdx.x;
    const int tid = threadIdx.x;
    const float* a = Ain + (size_t)row * D;
    const float* b = Bin + (size_t)row * D;

    float vals[D / 256];
    float s = 0.f, s2 = 0.f;
    #pragma unroll
    for (int i = 0; i < D / 256; i++) {
        int idx = tid + i * 256;
        float v = a[idx] + b[idx];
        vals[i] = v;
        s += v;
        s2 += v * v;
    }
    // warp reduce
    #pragma unroll
    for (int off = 16; off > 0; off >>= 1) {
        s  += __shfl_xor_sync(0xffffffffu, s,  off);
        s2 += __shfl_xor_sync(0xffffffffu, s2, off);
    }
    __shared__ float sh[2][8];
    if ((tid & 31) == 0) { sh[0][tid >> 5] = s; sh[1][tid >> 5] = s2; }
    __syncthreads();
    float ts = 0.f, t2 = 0.f;
    #pragma unroll
    for (int w = 0; w < 8; w++) { ts += sh[0][w]; t2 += sh[1][w]; }

    const float mu  = ts * (1.f / D);
    const float var = t2 * (1.f / D) - mu * mu;
    const float inv = rsqrtf(var + 1e-5f);

    #pragma unroll
    for (int i = 0; i < D / 256; i++) {
        int idx = tid + i * 256;
        out[(size_t)row * D + idx] = (vals[i] - mu) * inv * g[idx] + be[idx];
    }
}

// ---------------- launch --------------------------------------------------
extern "C" void kernel_launch(void* const* d_in, const int* in_sizes, int n_in,
                              void* d_out, int out_size)
{
    const float* x    = (const float*)d_in[0];
    const float* Wq   = (const float*)d_in[1];
    const float* bq   = (const float*)d_in[2];
    const float* Wk   = (const float*)d_in[3];
    const float* bk   = (const float*)d_in[4];
    const float* Wv   = (const float*)d_in[5];
    const float* bv   = (const float*)d_in[6];
    const float* Wo   = (const float*)d_in[7];
    const float* bo   = (const float*)d_in[8];
    const float* ln1g = (const float*)d_in[9];
    const float* ln1b = (const float*)d_in[10];
    const float* W1   = (const float*)d_in[11];
    const float* b1   = (const float*)d_in[12];
    const float* W2   = (const float*)d_in[13];
    const float* b2   = (const float*)d_in[14];
    const float* ln2g = (const float*)d_in[15];
    const float* ln2b = (const float*)d_in[16];
    float* out = (float*)d_out;

    float *q, *k, *v, *ctx, *attn, *h, *ff1, *ff2;
    cudaGetSymbolAddress((void**)&q,    g_q);
    cudaGetSymbolAddress((void**)&k,    g_k);
    cudaGetSymbolAddress((void**)&v,    g_v);
    cudaGetSymbolAddress((void**)&ctx,  g_ctx);
    cudaGetSymbolAddress((void**)&attn, g_attn);
    cudaGetSymbolAddress((void**)&h,    g_h);
    cudaGetSymbolAddress((void**)&ff1,  g_ff1);
    cudaGetSymbolAddress((void**)&ff2,  g_ff2);

    dim3 gProj(D / 128, MTOK / 128);       // (8, 32)
    sgemm_bias<0><<<gProj, 256>>>(x, Wq, bq, q, MTOK, D, D);
    sgemm_bias<0><<<gProj, 256>>>(x, Wk, bk, k, MTOK, D, D);
    sgemm_bias<0><<<gProj, 256>>>(x, Wv, bv, v, MTOK, D, D);

    dim3 gAttn(SEQ / 128, NH, BATCH);      // (16, 16, 2)
    attn_kernel<<<gAttn, 128>>>(q, k, v, ctx);

    sgemm_bias<0><<<gProj, 256>>>(ctx, Wo, bo, attn, MTOK, D, D);

    add_ln<<<MTOK, 256>>>(attn, x, ln1g, ln1b, h);

    dim3 gFF1(FF / 128, MTOK / 128);       // (32, 32)
    sgemm_bias<1><<<gFF1, 256>>>(h, W1, b1, ff1, MTOK, FF, D);

    dim3 gFF2(D / 128, MTOK / 128);        // (8, 32)
    sgemm_bias<0><<<gFF2, 256>>>(ff1, W2, b2, ff2, MTOK, D, FF);

    add_ln<<<MTOK, 256>>>(ff2, h, ln2g, ln2b, out);
}

// round 3
// speedup vs baseline: 1.6613x; 1.6613x over previous
#include <cuda_runtime.h>
#include <cuda_bf16.h>
#include <stdint.h>
#include <math.h>

#define D     1024
#define NH    16
#define HD    64
#define FF    4096
#define SEQ   2048
#define BATCH 2
#define MTOK  (BATCH*SEQ)   // 4096 rows

// ---------------- scratch (static device globals; no allocs) ----------------
__device__ float g_q[MTOK*(size_t)D];
__device__ float g_k[MTOK*(size_t)D];
__device__ float g_v[MTOK*(size_t)D];
__device__ float g_attn[MTOK*(size_t)D];
__device__ float g_h[MTOK*(size_t)D];
__device__ float g_ff2[MTOK*(size_t)D];

__device__ __nv_bfloat16 g_xh[MTOK*(size_t)D],  g_xl[MTOK*(size_t)D];
__device__ __nv_bfloat16 g_ctxh[MTOK*(size_t)D], g_ctxl[MTOK*(size_t)D];
__device__ __nv_bfloat16 g_hh[MTOK*(size_t)D],  g_hl[MTOK*(size_t)D];
__device__ __nv_bfloat16 g_f1h[MTOK*(size_t)FF], g_f1l[MTOK*(size_t)FF];
__device__ __nv_bfloat16 g_wqh[D*(size_t)D], g_wql[D*(size_t)D];
__device__ __nv_bfloat16 g_wkh[D*(size_t)D], g_wkl[D*(size_t)D];
__device__ __nv_bfloat16 g_wvh[D*(size_t)D], g_wvl[D*(size_t)D];
__device__ __nv_bfloat16 g_woh[D*(size_t)D], g_wol[D*(size_t)D];
__device__ __nv_bfloat16 g_w1h[D*(size_t)FF], g_w1l[D*(size_t)FF];
__device__ __nv_bfloat16 g_w2h[D*(size_t)FF], g_w2l[D*(size_t)FF];

// ---------------- helpers --------------------------------------------------
__device__ __forceinline__ unsigned smem_u32(const void* p) {
    return (unsigned)__cvta_generic_to_shared(p);
}
__device__ __forceinline__ void ldsm_x4(unsigned r[4], unsigned addr) {
    asm volatile("ldmatrix.sync.aligned.m8n8.x4.shared.b16 {%0,%1,%2,%3}, [%4];"
                 : "=r"(r[0]), "=r"(r[1]), "=r"(r[2]), "=r"(r[3]) : "r"(addr));
}
__device__ __forceinline__ void ldsm_x2t(unsigned r[2], unsigned addr) {
    asm volatile("ldmatrix.sync.aligned.m8n8.x2.trans.shared.b16 {%0,%1}, [%2];"
                 : "=r"(r[0]), "=r"(r[1]) : "r"(addr));
}
__device__ __forceinline__ void mma_bf16(float c[4], const unsigned a[4], const unsigned b[2]) {
    asm volatile("mma.sync.aligned.m16n8k16.row.col.f32.bf16.bf16.f32 "
                 "{%0,%1,%2,%3}, {%4,%5,%6,%7}, {%8,%9}, {%0,%1,%2,%3};"
                 : "+f"(c[0]), "+f"(c[1]), "+f"(c[2]), "+f"(c[3])
                 : "r"(a[0]), "r"(a[1]), "r"(a[2]), "r"(a[3]), "r"(b[0]), "r"(b[1]));
}
__device__ __forceinline__ void cp16(unsigned dst, const void* src) {
    asm volatile("cp.async.cg.shared.global [%0], [%1], 16;" :: "r"(dst), "l"(src) : "memory");
}
__device__ __forceinline__ void cp_commit() { asm volatile("cp.async.commit_group;" ::: "memory"); }
template <int N>
__device__ __forceinline__ void cp_wait() { asm volatile("cp.async.wait_group %0;" :: "n"(N) : "memory"); }

// smem tile layout (padded for conflict-free ldmatrix)
#define AS 40    // A row stride (bf16), 128x32 tile
#define BS 136   // B row stride (bf16), 32x128 tile
struct SmemT {
    __nv_bfloat16 Ah[2][128][AS];
    __nv_bfloat16 Al[2][128][AS];
    __nv_bfloat16 Bh[2][32][BS];
    __nv_bfloat16 Bl[2][32][BS];
};

// ---------------- bf16x3 tensor-core GEMM ----------------------------------
// C[M,N] = A[M,K] @ B[K,N] + bias.  A,B given as bf16 hi/lo splits.
// EPI: 0 = write fp32 C;  1 = exact erf-GELU then write bf16 hi/lo (Ch,Cl)
template <int EPI>
__global__ __launch_bounds__(256, 1) void gemm_bf16x3(
    const __nv_bfloat16* __restrict__ Agh, const __nv_bfloat16* __restrict__ Agl,
    const __nv_bfloat16* __restrict__ Bgh, const __nv_bfloat16* __restrict__ Bgl,
    const float* __restrict__ bias,
    float* __restrict__ C, __nv_bfloat16* __restrict__ Ch, __nv_bfloat16* __restrict__ Cl,
    int M, int N, int K)
{
    extern __shared__ char smem_raw[];
    SmemT& sm = *reinterpret_cast<SmemT*>(smem_raw);

    const int tid  = threadIdx.x;
    const int lane = tid & 31;
    const int wid  = tid >> 5;
    const int warpM = wid & 1;     // 2 warps in M
    const int warpN = wid >> 1;    // 4 warps in N
    const int bx = blockIdx.x;     // N tile
    const int by = blockIdx.y;     // M tile

    const int KT = K / 32;

    float acc[4][4][4];
    #pragma unroll
    for (int i = 0; i < 4; i++)
        #pragma unroll
        for (int j = 0; j < 4; j++)
            #pragma unroll
            for (int r = 0; r < 4; r++) acc[i][j][r] = 0.f;

    auto load_stage = [&](int st, int kt) {
        #pragma unroll
        for (int l = 0; l < 2; l++) {
            int f = tid + l * 256;
            int r = f >> 2, c = (f & 3) * 8;
            const size_t goff = (size_t)(by * 128 + r) * K + kt * 32 + c;
            cp16(smem_u32(&sm.Ah[st][r][c]), Agh + goff);
            cp16(smem_u32(&sm.Al[st][r][c]), Agl + goff);
        }
        #pragma unroll
        for (int l = 0; l < 2; l++) {
            int f = tid + l * 256;
            int r = f >> 4, c = (f & 15) * 8;
            const size_t goff = (size_t)(kt * 32 + r) * N + bx * 128 + c;
            cp16(smem_u32(&sm.Bh[st][r][c]), Bgh + goff);
            cp16(smem_u32(&sm.Bl[st][r][c]), Bgl + goff);
        }
    };

    load_stage(0, 0);
    cp_commit();

    const int lrow = lane & 15;
    const int lcol8 = (lane >> 4) * 8;

    for (int kt = 0; kt < KT; kt++) {
        int st = kt & 1;
        if (kt + 1 < KT) load_stage(st ^ 1, kt + 1);
        cp_commit();
        cp_wait<1>();
        __syncthreads();

        #pragma unroll
        for (int ks = 0; ks < 2; ks++) {
            const int k0 = ks * 16;
            unsigned ah[4][4], al[4][4], bh[4][2], bl[4][2];
            #pragma unroll
            for (int mi = 0; mi < 4; mi++) {
                int r = warpM * 64 + mi * 16 + lrow;
                int c = k0 + lcol8;
                ldsm_x4(ah[mi], smem_u32(&sm.Ah[st][r][c]));
                ldsm_x4(al[mi], smem_u32(&sm.Al[st][r][c]));
            }
            #pragma unroll
            for (int ni = 0; ni < 4; ni++) {
                int rk = k0 + lrow;
                int cn = warpN * 32 + ni * 8;
                ldsm_x2t(bh[ni], smem_u32(&sm.Bh[st][rk][cn]));
                ldsm_x2t(bl[ni], smem_u32(&sm.Bl[st][rk][cn]));
            }
            #pragma unroll
            for (int mi = 0; mi < 4; mi++)
                #pragma unroll
                for (int ni = 0; ni < 4; ni++) {
                    mma_bf16(acc[mi][ni], ah[mi], bh[ni]);
                    mma_bf16(acc[mi][ni], al[mi], bh[ni]);
                    mma_bf16(acc[mi][ni], ah[mi], bl[ni]);
                }
        }
        __syncthreads();
    }
    cp_wait<0>();

    // epilogue
    const int g  = lane >> 2;
    const int t2 = (lane & 3) * 2;
    #pragma unroll
    for (int mi = 0; mi < 4; mi++) {
        #pragma unroll
        for (int ni = 0; ni < 4; ni++) {
            int row0 = by * 128 + warpM * 64 + mi * 16 + g;
            int col  = bx * 128 + warpN * 32 + ni * 8 + t2;
            float b0 = bias[col], b1 = bias[col + 1];
            #pragma unroll
            for (int half = 0; half < 2; half++) {
                int row = row0 + half * 8;
                float v0 = acc[mi][ni][half * 2 + 0] + b0;
                float v1 = acc[mi][ni][half * 2 + 1] + b1;
                if (EPI == 1) {
                    v0 = 0.5f * v0 * (1.f + erff(v0 * 0.70710678118654752f));
                    v1 = 0.5f * v1 * (1.f + erff(v1 * 0.70710678118654752f));
                    __nv_bfloat16 h0 = __float2bfloat16_rn(v0);
                    __nv_bfloat16 h1 = __float2bfloat16_rn(v1);
                    __nv_bfloat16 l0 = __float2bfloat16_rn(v0 - __bfloat162float(h0));
                    __nv_bfloat16 l1 = __float2bfloat16_rn(v1 - __bfloat162float(h1));
                    *(__nv_bfloat162*)(Ch + (size_t)row * N + col) = __nv_bfloat162(h0, h1);
                    *(__nv_bfloat162*)(Cl + (size_t)row * N + col) = __nv_bfloat162(l0, l1);
                } else {
                    float2 o; o.x = v0; o.y = v1;
                    *(float2*)(C + (size_t)row * N + col) = o;
                }
            }
        }
    }
}

// ---------------- fp32 -> bf16 hi/lo split ---------------------------------
__global__ void split_bf16(const float* __restrict__ src,
                           __nv_bfloat16* __restrict__ hi, __nv_bfloat16* __restrict__ lo, int n)
{
    int i = (blockIdx.x * blockDim.x + threadIdx.x) * 2;
    if (i >= n) return;
    float2 v = *(const float2*)(src + i);
    __nv_bfloat16 h0 = __float2bfloat16_rn(v.x);
    __nv_bfloat16 h1 = __float2bfloat16_rn(v.y);
    __nv_bfloat16 l0 = __float2bfloat16_rn(v.x - __bfloat162float(h0));
    __nv_bfloat16 l1 = __float2bfloat16_rn(v.y - __bfloat162float(h1));
    *(__nv_bfloat162*)(hi + i) = __nv_bfloat162(h0, h1);
    *(__nv_bfloat162*)(lo + i) = __nv_bfloat162(l0, l1);
}

// ---------------- causal flash attention (fp32) -----------------------------
// writes ctx as bf16 hi/lo for the O projection
__global__ __launch_bounds__(128) void attn_kernel(
    const float* __restrict__ q, const float* __restrict__ k,
    const float* __restrict__ v,
    __nv_bfloat16* __restrict__ ctxh, __nv_bfloat16* __restrict__ ctxl)
{
    __shared__ float Ks[64][HD];
    __shared__ float Vs[64][HD];

    const int tid = threadIdx.x;
    const int qi  = blockIdx.x * 128 + tid;
    const int h   = blockIdx.y;
    const int b   = blockIdx.z;
    const float scale = 0.125f;

    float qr[HD];
    const float* qp = q + ((size_t)(b * SEQ + qi)) * D + h * HD;
    #pragma unroll
    for (int d = 0; d < HD; d++) qr[d] = qp[d] * scale;

    float m = -1e30f, l = 0.f;
    float acc[HD];
    #pragma unroll
    for (int d = 0; d < HD; d++) acc[d] = 0.f;

    const int ktiles = blockIdx.x * 2 + 2;

    for (int kt = 0; kt < ktiles; kt++) {
        __syncthreads();
        const float* kbase = k + ((size_t)(b * SEQ + kt * 64)) * D + h * HD;
        const float* vbase = v + ((size_t)(b * SEQ + kt * 64)) * D + h * HD;
        for (int f = tid; f < 64 * (HD / 4); f += 128) {
            int row = f >> 4;
            int c4  = f & 15;
            *(float4*)(&Ks[row][c4*4]) = *(const float4*)(kbase + (size_t)row * D + c4 * 4);
            *(float4*)(&Vs[row][c4*4]) = *(const float4*)(vbase + (size_t)row * D + c4 * 4);
        }
        __syncthreads();

        int kmax = qi - kt * 64 + 1;
        if (kmax > 64) kmax = 64;
        for (int kk = 0; kk < kmax; kk++) {
            float s = 0.f;
            #pragma unroll
            for (int d = 0; d < HD; d++) s = fmaf(qr[d], Ks[kk][d], s);
            if (s > m) {
                float c = __expf(m - s);
                l *= c;
                #pragma unroll
                for (int d = 0; d < HD; d++) acc[d] *= c;
                m = s;
            }
            float p = __expf(s - m);
            l += p;
            #pragma unroll
            for (int d = 0; d < HD; d++) acc[d] = fmaf(p, Vs[kk][d], acc[d]);
        }
    }

    float inv = 1.f / l;
    size_t obase = ((size_t)(b * SEQ + qi)) * D + h * HD;
    #pragma unroll
    for (int d = 0; d < HD; d += 2) {
        float r0 = acc[d] * inv, r1 = acc[d + 1] * inv;
        __nv_bfloat16 h0 = __float2bfloat16_rn(r0);
        __nv_bfloat16 h1 = __float2bfloat16_rn(r1);
        __nv_bfloat16 l0 = __float2bfloat16_rn(r0 - __bfloat162float(h0));
        __nv_bfloat16 l1 = __float2bfloat16_rn(r1 - __bfloat162float(h1));
        *(__nv_bfloat162*)(ctxh + obase + d) = __nv_bfloat162(h0, h1);
        *(__nv_bfloat162*)(ctxl + obase + d) = __nv_bfloat162(l0, l1);
    }
}

// ---------------- fused residual add + LayerNorm ----------------------------
// WB=1: additionally write bf16 hi/lo split of output
template <int WB>
__global__ __launch_bounds__(256) void add_ln(
    const float* __restrict__ Ain, const float* __restrict__ Bin,
    const float* __restrict__ g, const float* __restrict__ be,
    float* __restrict__ out,
    __nv_bfloat16* __restrict__ oh, __nv_bfloat16* __restrict__ ol)
{
    const int row = blockIdx.x;
    const int tid = threadIdx.x;
    const float* a = Ain + (size_t)row * D;
    const float* b = Bin + (size_t)row * D;

    float vals[D / 256];
    float s = 0.f, s2 = 0.f;
    #pragma unroll
    for (int i = 0; i < D / 256; i++) {
        int idx = tid + i * 256;
        float v = a[idx] + b[idx];
        vals[i] = v;
        s += v;
        s2 += v * v;
    }
    #pragma unroll
    for (int off = 16; off > 0; off >>= 1) {
        s  += __shfl_xor_sync(0xffffffffu, s,  off);
        s2 += __shfl_xor_sync(0xffffffffu, s2, off);
    }
    __shared__ float sh[2][8];
    if ((tid & 31) == 0) { sh[0][tid >> 5] = s; sh[1][tid >> 5] = s2; }
    __syncthreads();
    float ts = 0.f, t2 = 0.f;
    #pragma unroll
    for (int w = 0; w < 8; w++) { ts += sh[0][w]; t2 += sh[1][w]; }

    const float mu  = ts * (1.f / D);
    const float var = t2 * (1.f / D) - mu * mu;
    const float inv = rsqrtf(var + 1e-5f);

    #pragma unroll
    for (int i = 0; i < D / 256; i++) {
        int idx = tid + i * 256;
        float o = (vals[i] - mu) * inv * g[idx] + be[idx];
        out[(size_t)row * D + idx] = o;
        if (WB) {
            __nv_bfloat16 h = __float2bfloat16_rn(o);
            __nv_bfloat16 lo2 = __float2bfloat16_rn(o - __bfloat162float(h));
            oh[(size_t)row * D + idx] = h;
            ol[(size_t)row * D + idx] = lo2;
        }
    }
}

// ---------------- launch -----------------------------------------------------
extern "C" void kernel_launch(void* const* d_in, const int* in_sizes, int n_in,
                              void* d_out, int out_size)
{
    const float* x    = (const float*)d_in[0];
    const float* Wq   = (const float*)d_in[1];
    const float* bq   = (const float*)d_in[2];
    const float* Wk   = (const float*)d_in[3];
    const float* bk   = (const float*)d_in[4];
    const float* Wv   = (const float*)d_in[5];
    const float* bv   = (const float*)d_in[6];
    const float* Wo   = (const float*)d_in[7];
    const float* bo   = (const float*)d_in[8];
    const float* ln1g = (const float*)d_in[9];
    const float* ln1b = (const float*)d_in[10];
    const float* W1   = (const float*)d_in[11];
    const float* b1   = (const float*)d_in[12];
    const float* W2   = (const float*)d_in[13];
    const float* b2   = (const float*)d_in[14];
    const float* ln2g = (const float*)d_in[15];
    const float* ln2b = (const float*)d_in[16];
    float* out = (float*)d_out;

    float *q, *k, *v, *attn, *h, *ff2;
    cudaGetSymbolAddress((void**)&q,    g_q);
    cudaGetSymbolAddress((void**)&k,    g_k);
    cudaGetSymbolAddress((void**)&v,    g_v);
    cudaGetSymbolAddress((void**)&attn, g_attn);
    cudaGetSymbolAddress((void**)&h,    g_h);
    cudaGetSymbolAddress((void**)&ff2,  g_ff2);

    __nv_bfloat16 *xh,*xl,*ctxh,*ctxl,*hh,*hl,*f1h,*f1l;
    __nv_bfloat16 *wqh,*wql,*wkh,*wkl,*wvh,*wvl,*woh,*wol,*w1h,*w1l,*w2h,*w2l;
    cudaGetSymbolAddress((void**)&xh, g_xh);   cudaGetSymbolAddress((void**)&xl, g_xl);
    cudaGetSymbolAddress((void**)&ctxh, g_ctxh); cudaGetSymbolAddress((void**)&ctxl, g_ctxl);
    cudaGetSymbolAddress((void**)&hh, g_hh);   cudaGetSymbolAddress((void**)&hl, g_hl);
    cudaGetSymbolAddress((void**)&f1h, g_f1h); cudaGetSymbolAddress((void**)&f1l, g_f1l);
    cudaGetSymbolAddress((void**)&wqh, g_wqh); cudaGetSymbolAddress((void**)&wql, g_wql);
    cudaGetSymbolAddress((void**)&wkh, g_wkh); cudaGetSymbolAddress((void**)&wkl, g_wkl);
    cudaGetSymbolAddress((void**)&wvh, g_wvh); cudaGetSymbolAddress((void**)&wvl, g_wvl);
    cudaGetSymbolAddress((void**)&woh, g_woh); cudaGetSymbolAddress((void**)&wol, g_wol);
    cudaGetSymbolAddress((void**)&w1h, g_w1h); cudaGetSymbolAddress((void**)&w1l, g_w1l);
    cudaGetSymbolAddress((void**)&w2h, g_w2h); cudaGetSymbolAddress((void**)&w2l, g_w2l);

    static int smem_set = 0;
    if (!smem_set) {
        cudaFuncSetAttribute(gemm_bf16x3<0>, cudaFuncAttributeMaxDynamicSharedMemorySize, (int)sizeof(SmemT));
        cudaFuncSetAttribute(gemm_bf16x3<1>, cudaFuncAttributeMaxDynamicSharedMemorySize, (int)sizeof(SmemT));
        smem_set = 1;
    }
    const int SB = (int)sizeof(SmemT);

    // ---- splits ----
    int n;
    n = MTOK * D;  split_bf16<<<(n/2 + 255)/256, 256>>>(x,  xh,  xl,  n);
    n = D * D;     split_bf16<<<(n/2 + 255)/256, 256>>>(Wq, wqh, wql, n);
    n = D * D;     split_bf16<<<(n/2 + 255)/256, 256>>>(Wk, wkh, wkl, n);
    n = D * D;     split_bf16<<<(n/2 + 255)/256, 256>>>(Wv, wvh, wvl, n);
    n = D * D;     split_bf16<<<(n/2 + 255)/256, 256>>>(Wo, woh, wol, n);
    n = D * FF;    split_bf16<<<(n/2 + 255)/256, 256>>>(W1, w1h, w1l, n);
    n = D * FF;    split_bf16<<<(n/2 + 255)/256, 256>>>(W2, w2h, w2l, n);

    // ---- QKV ----
    dim3 gProj(D / 128, MTOK / 128);
    gemm_bf16x3<0><<<gProj, 256, SB>>>(xh, xl, wqh, wql, bq, q, nullptr, nullptr, MTOK, D, D);
    gemm_bf16x3<0><<<gProj, 256, SB>>>(xh, xl, wkh, wkl, bk, k, nullptr, nullptr, MTOK, D, D);
    gemm_bf16x3<0><<<gProj, 256, SB>>>(xh, xl, wvh, wvl, bv, v, nullptr, nullptr, MTOK, D, D);

    // ---- attention ----
    dim3 gAttn(SEQ / 128, NH, BATCH);
    attn_kernel<<<gAttn, 128>>>(q, k, v, ctxh, ctxl);

    // ---- O projection ----
    gemm_bf16x3<0><<<gProj, 256, SB>>>(ctxh, ctxl, woh, wol, bo, attn, nullptr, nullptr, MTOK, D, D);

    // ---- LN1 (also emits bf16 split of h) ----
    add_ln<1><<<MTOK, 256>>>(attn, x, ln1g, ln1b, h, hh, hl);

    // ---- FFN ----
    dim3 gFF1(FF / 128, MTOK / 128);
    gemm_bf16x3<1><<<gFF1, 256, SB>>>(hh, hl, w1h, w1l, b1, nullptr, f1h, f1l, MTOK, FF, D);

    dim3 gFF2(D / 128, MTOK / 128);
    gemm_bf16x3<0><<<gFF2, 256, SB>>>(f1h, f1l, w2h, w2l, b2, ff2, nullptr, nullptr, MTOK, D, FF);

    // ---- LN2 ----
    add_ln<0><<<MTOK, 256>>>(ff2, h, ln2g, ln2b, out, nullptr, nullptr);
}

// round 4
// speedup vs baseline: 2.6838x; 1.6155x over previous
#include <cuda_runtime.h>
#include <cuda_bf16.h>
#include <stdint.h>
#include <math.h>

#define D     1024
#define NH    16
#define HD    64
#define FF    4096
#define SEQ   2048
#define BATCH 2
#define MTOK  (BATCH*SEQ)   // 4096 rows

// ---------------- scratch (static device globals; no allocs) ----------------
__device__ float g_attn[MTOK*(size_t)D];
__device__ float g_h[MTOK*(size_t)D];
__device__ float g_ff2[MTOK*(size_t)D];

__device__ __nv_bfloat16 g_xh[MTOK*(size_t)D],  g_xl[MTOK*(size_t)D];
__device__ __nv_bfloat16 g_qh[MTOK*(size_t)D],  g_ql[MTOK*(size_t)D];
__device__ __nv_bfloat16 g_kh[MTOK*(size_t)D],  g_kl[MTOK*(size_t)D];
__device__ __nv_bfloat16 g_vh[MTOK*(size_t)D],  g_vl[MTOK*(size_t)D];
__device__ __nv_bfloat16 g_ctxh[MTOK*(size_t)D], g_ctxl[MTOK*(size_t)D];
__device__ __nv_bfloat16 g_hh[MTOK*(size_t)D],  g_hl[MTOK*(size_t)D];
__device__ __nv_bfloat16 g_f1h[MTOK*(size_t)FF], g_f1l[MTOK*(size_t)FF];
__device__ __nv_bfloat16 g_wqh[D*(size_t)D], g_wql[D*(size_t)D];
__device__ __nv_bfloat16 g_wkh[D*(size_t)D], g_wkl[D*(size_t)D];
__device__ __nv_bfloat16 g_wvh[D*(size_t)D], g_wvl[D*(size_t)D];
__device__ __nv_bfloat16 g_woh[D*(size_t)D], g_wol[D*(size_t)D];
__device__ __nv_bfloat16 g_w1h[D*(size_t)FF], g_w1l[D*(size_t)FF];
__device__ __nv_bfloat16 g_w2h[D*(size_t)FF], g_w2l[D*(size_t)FF];

// ---------------- helpers --------------------------------------------------
__device__ __forceinline__ unsigned smem_u32(const void* p) {
    return (unsigned)__cvta_generic_to_shared(p);
}
__device__ __forceinline__ void ldsm_x4(unsigned r[4], unsigned addr) {
    asm volatile("ldmatrix.sync.aligned.m8n8.x4.shared.b16 {%0,%1,%2,%3}, [%4];"
                 : "=r"(r[0]), "=r"(r[1]), "=r"(r[2]), "=r"(r[3]) : "r"(addr));
}
__device__ __forceinline__ void ldsm_x2(unsigned r[2], unsigned addr) {
    asm volatile("ldmatrix.sync.aligned.m8n8.x2.shared.b16 {%0,%1}, [%2];"
                 : "=r"(r[0]), "=r"(r[1]) : "r"(addr));
}
__device__ __forceinline__ void ldsm_x2t(unsigned r[2], unsigned addr) {
    asm volatile("ldmatrix.sync.aligned.m8n8.x2.trans.shared.b16 {%0,%1}, [%2];"
                 : "=r"(r[0]), "=r"(r[1]) : "r"(addr));
}
__device__ __forceinline__ void mma_bf16(float c[4], const unsigned a[4], const unsigned b[2]) {
    asm volatile("mma.sync.aligned.m16n8k16.row.col.f32.bf16.bf16.f32 "
                 "{%0,%1,%2,%3}, {%4,%5,%6,%7}, {%8,%9}, {%0,%1,%2,%3};"
                 : "+f"(c[0]), "+f"(c[1]), "+f"(c[2]), "+f"(c[3])
                 : "r"(a[0]), "r"(a[1]), "r"(a[2]), "r"(a[3]), "r"(b[0]), "r"(b[1]));
}
__device__ __forceinline__ void cp16(unsigned dst, const void* src) {
    asm volatile("cp.async.cg.shared.global [%0], [%1], 16;" :: "r"(dst), "l"(src) : "memory");
}
__device__ __forceinline__ void cp_commit() { asm volatile("cp.async.commit_group;" ::: "memory"); }
template <int N>
__device__ __forceinline__ void cp_wait() { asm volatile("cp.async.wait_group %0;" :: "n"(N) : "memory"); }

__device__ __forceinline__ unsigned pack_bf16x2(float a, float b) {
    __nv_bfloat162 p = __floats2bfloat162_rn(a, b);
    return *(unsigned*)&p;
}

// ==================== GEMM ====================
#define AS 40
#define BS 136
struct SmemT {
    __nv_bfloat16 Ah[2][128][AS];
    __nv_bfloat16 Al[2][128][AS];
    __nv_bfloat16 Bh[2][32][BS];
    __nv_bfloat16 Bl[2][32][BS];
};

// EPI: 0 = fp32 C; 1 = GELU then bf16 hi/lo; 2 = bf16 hi/lo (no act)
template <int EPI>
__global__ __launch_bounds__(256, 1) void gemm_bf16x3(
    const __nv_bfloat16* __restrict__ Agh, const __nv_bfloat16* __restrict__ Agl,
    const __nv_bfloat16* __restrict__ Bgh, const __nv_bfloat16* __restrict__ Bgl,
    const float* __restrict__ bias,
    float* __restrict__ C, __nv_bfloat16* __restrict__ Ch, __nv_bfloat16* __restrict__ Cl,
    int M, int N, int K)
{
    extern __shared__ char smem_raw[];
    SmemT& sm = *reinterpret_cast<SmemT*>(smem_raw);

    const int tid  = threadIdx.x;
    const int lane = tid & 31;
    const int wid  = tid >> 5;
    const int warpM = wid & 1;
    const int warpN = wid >> 1;
    const int bx = blockIdx.x;
    const int by = blockIdx.y;
    const int KT = K / 32;

    float acc[4][4][4];
    #pragma unroll
    for (int i = 0; i < 4; i++)
        #pragma unroll
        for (int j = 0; j < 4; j++)
            #pragma unroll
            for (int r = 0; r < 4; r++) acc[i][j][r] = 0.f;

    auto load_stage = [&](int st, int kt) {
        #pragma unroll
        for (int l = 0; l < 2; l++) {
            int f = tid + l * 256;
            int r = f >> 2, c = (f & 3) * 8;
            const size_t goff = (size_t)(by * 128 + r) * K + kt * 32 + c;
            cp16(smem_u32(&sm.Ah[st][r][c]), Agh + goff);
            cp16(smem_u32(&sm.Al[st][r][c]), Agl + goff);
        }
        #pragma unroll
        for (int l = 0; l < 2; l++) {
            int f = tid + l * 256;
            int r = f >> 4, c = (f & 15) * 8;
            const size_t goff = (size_t)(kt * 32 + r) * N + bx * 128 + c;
            cp16(smem_u32(&sm.Bh[st][r][c]), Bgh + goff);
            cp16(smem_u32(&sm.Bl[st][r][c]), Bgl + goff);
        }
    };

    load_stage(0, 0);
    cp_commit();

    const int lrow = lane & 15;
    const int lcol8 = (lane >> 4) * 8;

    for (int kt = 0; kt < KT; kt++) {
        int st = kt & 1;
        if (kt + 1 < KT) { load_stage(st ^ 1, kt + 1); cp_commit(); cp_wait<1>(); }
        else cp_wait<0>();
        __syncthreads();

        #pragma unroll
        for (int ks = 0; ks < 2; ks++) {
            const int k0 = ks * 16;
            unsigned ah[4][4], al[4][4], bh[4][2], bl[4][2];
            #pragma unroll
            for (int mi = 0; mi < 4; mi++) {
                int r = warpM * 64 + mi * 16 + lrow;
                int c = k0 + lcol8;
                ldsm_x4(ah[mi], smem_u32(&sm.Ah[st][r][c]));
                ldsm_x4(al[mi], smem_u32(&sm.Al[st][r][c]));
            }
            #pragma unroll
            for (int ni = 0; ni < 4; ni++) {
                int rk = k0 + lrow;
                int cn = warpN * 32 + ni * 8;
                ldsm_x2t(bh[ni], smem_u32(&sm.Bh[st][rk][cn]));
                ldsm_x2t(bl[ni], smem_u32(&sm.Bl[st][rk][cn]));
            }
            #pragma unroll
            for (int mi = 0; mi < 4; mi++)
                #pragma unroll
                for (int ni = 0; ni < 4; ni++) {
                    mma_bf16(acc[mi][ni], ah[mi], bh[ni]);
                    mma_bf16(acc[mi][ni], al[mi], bh[ni]);
                    mma_bf16(acc[mi][ni], ah[mi], bl[ni]);
                }
        }
        __syncthreads();
    }

    const int g  = lane >> 2;
    const int t2 = (lane & 3) * 2;
    #pragma unroll
    for (int mi = 0; mi < 4; mi++) {
        #pragma unroll
        for (int ni = 0; ni < 4; ni++) {
            int row0 = by * 128 + warpM * 64 + mi * 16 + g;
            int col  = bx * 128 + warpN * 32 + ni * 8 + t2;
            float b0 = bias[col], b1 = bias[col + 1];
            #pragma unroll
            for (int half = 0; half < 2; half++) {
                int row = row0 + half * 8;
                float v0 = acc[mi][ni][half * 2 + 0] + b0;
                float v1 = acc[mi][ni][half * 2 + 1] + b1;
                if (EPI >= 1) {
                    if (EPI == 1) {
                        v0 = 0.5f * v0 * (1.f + erff(v0 * 0.70710678118654752f));
                        v1 = 0.5f * v1 * (1.f + erff(v1 * 0.70710678118654752f));
                    }
                    __nv_bfloat16 h0 = __float2bfloat16_rn(v0);
                    __nv_bfloat16 h1 = __float2bfloat16_rn(v1);
                    __nv_bfloat16 l0 = __float2bfloat16_rn(v0 - __bfloat162float(h0));
                    __nv_bfloat16 l1 = __float2bfloat16_rn(v1 - __bfloat162float(h1));
                    *(__nv_bfloat162*)(Ch + (size_t)row * N + col) = __nv_bfloat162(h0, h1);
                    *(__nv_bfloat162*)(Cl + (size_t)row * N + col) = __nv_bfloat162(l0, l1);
                } else {
                    float2 o; o.x = v0; o.y = v1;
                    *(float2*)(C + (size_t)row * N + col) = o;
                }
            }
        }
    }
}

// ---------------- fp32 -> bf16 hi/lo split ---------------------------------
__global__ void split_bf16(const float* __restrict__ src,
                           __nv_bfloat16* __restrict__ hi, __nv_bfloat16* __restrict__ lo, int n)
{
    int i = (blockIdx.x * blockDim.x + threadIdx.x) * 2;
    if (i >= n) return;
    float2 v = *(const float2*)(src + i);
    __nv_bfloat16 h0 = __float2bfloat16_rn(v.x);
    __nv_bfloat16 h1 = __float2bfloat16_rn(v.y);
    __nv_bfloat16 l0 = __float2bfloat16_rn(v.x - __bfloat162float(h0));
    __nv_bfloat16 l1 = __float2bfloat16_rn(v.y - __bfloat162float(h1));
    *(__nv_bfloat162*)(hi + i) = __nv_bfloat162(h0, h1);
    *(__nv_bfloat162*)(lo + i) = __nv_bfloat162(l0, l1);
}

// ==================== tensor-core flash attention ====================
// block = 256 threads (8 warps), each warp = 16 query rows; 128 queries x 1 head.
#define QPAD 72
struct AttnSmem {
    __nv_bfloat16 Qh[128][QPAD], Ql[128][QPAD];
    __nv_bfloat16 Kh[2][64][QPAD], Kl[2][64][QPAD];
    __nv_bfloat16 Vh[2][64][QPAD], Vl[2][64][QPAD];
};

__global__ __launch_bounds__(256, 1) void attn_mma(
    const __nv_bfloat16* __restrict__ qh, const __nv_bfloat16* __restrict__ ql,
    const __nv_bfloat16* __restrict__ kh, const __nv_bfloat16* __restrict__ kl,
    const __nv_bfloat16* __restrict__ vh, const __nv_bfloat16* __restrict__ vl,
    __nv_bfloat16* __restrict__ ctxh, __nv_bfloat16* __restrict__ ctxl)
{
    extern __shared__ char smem_raw[];
    AttnSmem& sm = *reinterpret_cast<AttnSmem*>(smem_raw);

    const int tid  = threadIdx.x;
    const int lane = tid & 31;
    const int w    = tid >> 5;
    const int g    = lane >> 2;
    const int t    = lane & 3;

    const int qt = (int)gridDim.x - 1 - (int)blockIdx.x;   // reverse for load balance
    const int h  = blockIdx.y;
    const int b  = blockIdx.z;
    const size_t q0 = (size_t)b * SEQ + qt * 128;          // global row of first query
    const int hcol = h * HD;

    // issue Q tile loads (group with stage 0)
    #pragma unroll
    for (int l = 0; l < 4; l++) {
        int f = tid + l * 256;
        int r = f >> 3, c = (f & 7) * 8;
        cp16(smem_u32(&sm.Qh[r][c]), qh + (q0 + r) * D + hcol + c);
        cp16(smem_u32(&sm.Ql[r][c]), ql + (q0 + r) * D + hcol + c);
    }

    auto load_kv = [&](int st, int kt) {
        const size_t kr0 = (size_t)b * SEQ + kt * 64;
        #pragma unroll
        for (int l = 0; l < 2; l++) {
            int f = tid + l * 256;
            int r = f >> 3, c = (f & 7) * 8;
            const size_t go = (kr0 + r) * D + hcol + c;
            cp16(smem_u32(&sm.Kh[st][r][c]), kh + go);
            cp16(smem_u32(&sm.Kl[st][r][c]), kl + go);
            cp16(smem_u32(&sm.Vh[st][r][c]), vh + go);
            cp16(smem_u32(&sm.Vl[st][r][c]), vl + go);
        }
    };

    load_kv(0, 0);
    cp_commit();

    const int ktiles = qt * 2 + 2;

    unsigned qfh[4][4], qfl[4][4];     // Q fragments (loaded at kt==0)
    float m[2] = {-1e30f, -1e30f};
    float lsum[2] = {0.f, 0.f};
    float acc[8][4];
    #pragma unroll
    for (int nf = 0; nf < 8; nf++)
        #pragma unroll
        for (int i = 0; i < 4; i++) acc[nf][i] = 0.f;

    for (int kt = 0; kt < ktiles; kt++) {
        const int st = kt & 1;
        if (kt + 1 < ktiles) { load_kv(st ^ 1, kt + 1); cp_commit(); cp_wait<1>(); }
        else cp_wait<0>();
        __syncthreads();

        if (kt == 0) {
            #pragma unroll
            for (int kf = 0; kf < 4; kf++) {
                int r = w * 16 + (lane & 15);
                int c = kf * 16 + (lane >> 4) * 8;
                ldsm_x4(qfh[kf], smem_u32(&sm.Qh[r][c]));
                ldsm_x4(qfl[kf], smem_u32(&sm.Ql[r][c]));
            }
        }

        // ---- S = Q K^T (bf16 split-3) ----
        float s[8][4];
        #pragma unroll
        for (int nf = 0; nf < 8; nf++)
            #pragma unroll
            for (int i = 0; i < 4; i++) s[nf][i] = 0.f;

        #pragma unroll
        for (int nf = 0; nf < 8; nf++) {
            #pragma unroll
            for (int kf = 0; kf < 4; kf++) {
                unsigned kbh[2], kbl[2];
                int kr = nf * 8 + (lane & 7);
                int kc = kf * 16 + ((lane >> 3) & 1) * 8;
                ldsm_x2(kbh, smem_u32(&sm.Kh[st][kr][kc]));
                ldsm_x2(kbl, smem_u32(&sm.Kl[st][kr][kc]));
                mma_bf16(s[nf], qfh[kf], kbh);
                mma_bf16(s[nf], qfl[kf], kbh);
                mma_bf16(s[nf], qfh[kf], kbl);
            }
        }

        // ---- scale + causal mask ----
        const int kbase = kt * 64;
        const int qbase = qt * 128 + w * 16;
        #pragma unroll
        for (int nf = 0; nf < 8; nf++) {
            #pragma unroll
            for (int i = 0; i < 4; i++) {
                int key = kbase + nf * 8 + 2 * t + (i & 1);
                int qry = qbase + g + (i >> 1) * 8;
                float sv = s[nf][i] * 0.125f;
                s[nf][i] = (key > qry) ? -1e30f : sv;
            }
        }

        // ---- online softmax ----
        float cfac[2];
        #pragma unroll
        for (int r = 0; r < 2; r++) {
            float vmax = -1e30f;
            #pragma unroll
            for (int nf = 0; nf < 8; nf++) {
                vmax = fmaxf(vmax, s[nf][2 * r]);
                vmax = fmaxf(vmax, s[nf][2 * r + 1]);
            }
            vmax = fmaxf(vmax, __shfl_xor_sync(0xffffffffu, vmax, 1));
            vmax = fmaxf(vmax, __shfl_xor_sync(0xffffffffu, vmax, 2));
            float mn = fmaxf(m[r], vmax);
            cfac[r] = __expf(m[r] - mn);
            m[r] = mn;
            float rowsum = 0.f;
            #pragma unroll
            for (int nf = 0; nf < 8; nf++) {
                float p0 = __expf(s[nf][2 * r]     - mn);
                float p1 = __expf(s[nf][2 * r + 1] - mn);
                s[nf][2 * r]     = p0;
                s[nf][2 * r + 1] = p1;
                rowsum += p0 + p1;
            }
            rowsum += __shfl_xor_sync(0xffffffffu, rowsum, 1);
            rowsum += __shfl_xor_sync(0xffffffffu, rowsum, 2);
            lsum[r] = lsum[r] * cfac[r] + rowsum;
        }
        // rescale accumulators
        #pragma unroll
        for (int nf = 0; nf < 8; nf++) {
            acc[nf][0] *= cfac[0]; acc[nf][1] *= cfac[0];
            acc[nf][2] *= cfac[1]; acc[nf][3] *= cfac[1];
        }

        // ---- pack P into bf16 hi/lo A-fragments ----
        unsigned pah[4][4], pal[4][4];
        #pragma unroll
        for (int kf = 0; kf < 4; kf++) {
            #pragma unroll
            for (int half = 0; half < 2; half++) {   // half 0: c0,c1 (row g); half 1: c2,c3 (row g+8)
                #pragma unroll
                for (int sub = 0; sub < 2; sub++) {  // sub: nf = 2kf+sub -> a-reg idx
                    int nf = 2 * kf + sub;
                    float p0 = s[nf][2 * half];
                    float p1 = s[nf][2 * half + 1];
                    __nv_bfloat16 h0 = __float2bfloat16_rn(p0);
                    __nv_bfloat16 h1 = __float2bfloat16_rn(p1);
                    float l0 = p0 - __bfloat162float(h0);
                    float l1 = p1 - __bfloat162float(h1);
                    unsigned hp; { __nv_bfloat162 tmp(h0, h1); hp = *(unsigned*)&tmp; }
                    pah[kf][sub * 2 + half] = hp;
                    pal[kf][sub * 2 + half] = pack_bf16x2(l0, l1);
                }
            }
        }

        // ---- acc += P V (bf16 split-3) ----
        #pragma unroll
        for (int nf = 0; nf < 8; nf++) {
            #pragma unroll
            for (int kf = 0; kf < 4; kf++) {
                unsigned vb[2], vbl[2];
                int vr = kf * 16 + (lane & 15);
                int vc = nf * 8;
                ldsm_x2t(vb,  smem_u32(&sm.Vh[st][vr][vc]));
                ldsm_x2t(vbl, smem_u32(&sm.Vl[st][vr][vc]));
                mma_bf16(acc[nf], pah[kf], vb);
                mma_bf16(acc[nf], pal[kf], vb);
                mma_bf16(acc[nf], pah[kf], vbl);
            }
        }
        __syncthreads();
    }

    // ---- epilogue: normalize, split to bf16 hi/lo, store ----
    const float inv0 = 1.f / lsum[0];
    const float inv1 = 1.f / lsum[1];
    #pragma unroll
    for (int nf = 0; nf < 8; nf++) {
        int col = hcol + nf * 8 + 2 * t;
        size_t row0 = q0 + w * 16 + g;
        float v0 = acc[nf][0] * inv0, v1 = acc[nf][1] * inv0;
        float v2 = acc[nf][2] * inv1, v3 = acc[nf][3] * inv1;
        __nv_bfloat16 h0 = __float2bfloat16_rn(v0), h1 = __float2bfloat16_rn(v1);
        __nv_bfloat16 h2 = __float2bfloat16_rn(v2), h3 = __float2bfloat16_rn(v3);
        *(__nv_bfloat162*)(ctxh + row0 * D + col) = __nv_bfloat162(h0, h1);
        *(__nv_bfloat162*)(ctxl + row0 * D + col) =
            __nv_bfloat162(__float2bfloat16_rn(v0 - __bfloat162float(h0)),
                           __float2bfloat16_rn(v1 - __bfloat162float(h1)));
        *(__nv_bfloat162*)(ctxh + (row0 + 8) * D + col) = __nv_bfloat162(h2, h3);
        *(__nv_bfloat162*)(ctxl + (row0 + 8) * D + col) =
            __nv_bfloat162(__float2bfloat16_rn(v2 - __bfloat162float(h2)),
                           __float2bfloat16_rn(v3 - __bfloat162float(h3)));
    }
}

// ---------------- fused residual add + LayerNorm ----------------------------
template <int WB>
__global__ __launch_bounds__(256) void add_ln(
    const float* __restrict__ Ain, const float* __restrict__ Bin,
    const float* __restrict__ g, const float* __restrict__ be,
    float* __restrict__ out,
    __nv_bfloat16* __restrict__ oh, __nv_bfloat16* __restrict__ ol)
{
    const int row = blockIdx.x;
    const int tid = threadIdx.x;
    const float* a = Ain + (size_t)row * D;
    const float* b = Bin + (size_t)row * D;

    float vals[D / 256];
    float s = 0.f, s2 = 0.f;
    #pragma unroll
    for (int i = 0; i < D / 256; i++) {
        int idx = tid + i * 256;
        float v = a[idx] + b[idx];
        vals[i] = v;
        s += v;
        s2 += v * v;
    }
    #pragma unroll
    for (int off = 16; off > 0; off >>= 1) {
        s  += __shfl_xor_sync(0xffffffffu, s,  off);
        s2 += __shfl_xor_sync(0xffffffffu, s2, off);
    }
    __shared__ float sh[2][8];
    if ((tid & 31) == 0) { sh[0][tid >> 5] = s; sh[1][tid >> 5] = s2; }
    __syncthreads();
    float ts = 0.f, t2 = 0.f;
    #pragma unroll
    for (int w = 0; w < 8; w++) { ts += sh[0][w]; t2 += sh[1][w]; }

    const float mu  = ts * (1.f / D);
    const float var = t2 * (1.f / D) - mu * mu;
    const float inv = rsqrtf(var + 1e-5f);

    #pragma unroll
    for (int i = 0; i < D / 256; i++) {
        int idx = tid + i * 256;
        float o = (vals[i] - mu) * inv * g[idx] + be[idx];
        out[(size_t)row * D + idx] = o;
        if (WB) {
            __nv_bfloat16 h = __float2bfloat16_rn(o);
            __nv_bfloat16 lo2 = __float2bfloat16_rn(o - __bfloat162float(h));
            oh[(size_t)row * D + idx] = h;
            ol[(size_t)row * D + idx] = lo2;
        }
    }
}

// ---------------- launch -----------------------------------------------------
extern "C" void kernel_launch(void* const* d_in, const int* in_sizes, int n_in,
                              void* d_out, int out_size)
{
    const float* x    = (const float*)d_in[0];
    const float* Wq   = (const float*)d_in[1];
    const float* bq   = (const float*)d_in[2];
    const float* Wk   = (const float*)d_in[3];
    const float* bk   = (const float*)d_in[4];
    const float* Wv   = (const float*)d_in[5];
    const float* bv   = (const float*)d_in[6];
    const float* Wo   = (const float*)d_in[7];
    const float* bo   = (const float*)d_in[8];
    const float* ln1g = (const float*)d_in[9];
    const float* ln1b = (const float*)d_in[10];
    const float* W1   = (const float*)d_in[11];
    const float* b1   = (const float*)d_in[12];
    const float* W2   = (const float*)d_in[13];
    const float* b2   = (const float*)d_in[14];
    const float* ln2g = (const float*)d_in[15];
    const float* ln2b = (const float*)d_in[16];
    float* out = (float*)d_out;

    float *attn, *h, *ff2;
    cudaGetSymbolAddress((void**)&attn, g_attn);
    cudaGetSymbolAddress((void**)&h,    g_h);
    cudaGetSymbolAddress((void**)&ff2,  g_ff2);

    __nv_bfloat16 *xh,*xl,*qh,*ql,*kh,*kl,*vh,*vl,*ctxh,*ctxl,*hh,*hl,*f1h,*f1l;
    __nv_bfloat16 *wqh,*wql,*wkh,*wkl,*wvh,*wvl,*woh,*wol,*w1h,*w1l,*w2h,*w2l;
    cudaGetSymbolAddress((void**)&xh, g_xh);   cudaGetSymbolAddress((void**)&xl, g_xl);
    cudaGetSymbolAddress((void**)&qh, g_qh);   cudaGetSymbolAddress((void**)&ql, g_ql);
    cudaGetSymbolAddress((void**)&kh, g_kh);   cudaGetSymbolAddress((void**)&kl, g_kl);
    cudaGetSymbolAddress((void**)&vh, g_vh);   cudaGetSymbolAddress((void**)&vl, g_vl);
    cudaGetSymbolAddress((void**)&ctxh, g_ctxh); cudaGetSymbolAddress((void**)&ctxl, g_ctxl);
    cudaGetSymbolAddress((void**)&hh, g_hh);   cudaGetSymbolAddress((void**)&hl, g_hl);
    cudaGetSymbolAddress((void**)&f1h, g_f1h); cudaGetSymbolAddress((void**)&f1l, g_f1l);
    cudaGetSymbolAddress((void**)&wqh, g_wqh); cudaGetSymbolAddress((void**)&wql, g_wql);
    cudaGetSymbolAddress((void**)&wkh, g_wkh); cudaGetSymbolAddress((void**)&wkl, g_wkl);
    cudaGetSymbolAddress((void**)&wvh, g_wvh); cudaGetSymbolAddress((void**)&wvl, g_wvl);
    cudaGetSymbolAddress((void**)&woh, g_woh); cudaGetSymbolAddress((void**)&wol, g_wol);
    cudaGetSymbolAddress((void**)&w1h, g_w1h); cudaGetSymbolAddress((void**)&w1l, g_w1l);
    cudaGetSymbolAddress((void**)&w2h, g_w2h); cudaGetSymbolAddress((void**)&w2l, g_w2l);

    static int attr_set = 0;
    if (!attr_set) {
        cudaFuncSetAttribute(gemm_bf16x3<0>, cudaFuncAttributeMaxDynamicSharedMemorySize, (int)sizeof(SmemT));
        cudaFuncSetAttribute(gemm_bf16x3<1>, cudaFuncAttributeMaxDynamicSharedMemorySize, (int)sizeof(SmemT));
        cudaFuncSetAttribute(gemm_bf16x3<2>, cudaFuncAttributeMaxDynamicSharedMemorySize, (int)sizeof(SmemT));
        cudaFuncSetAttribute(attn_mma, cudaFuncAttributeMaxDynamicSharedMemorySize, (int)sizeof(AttnSmem));
        attr_set = 1;
    }
    const int SB = (int)sizeof(SmemT);
    const int SA = (int)sizeof(AttnSmem);

    // ---- splits (inputs only) ----
    int n;
    n = MTOK * D;  split_bf16<<<(n/2 + 255)/256, 256>>>(x,  xh,  xl,  n);
    n = D * D;     split_bf16<<<(n/2 + 255)/256, 256>>>(Wq, wqh, wql, n);
    n = D * D;     split_bf16<<<(n/2 + 255)/256, 256>>>(Wk, wkh, wkl, n);
    n = D * D;     split_bf16<<<(n/2 + 255)/256, 256>>>(Wv, wvh, wvl, n);
    n = D * D;     split_bf16<<<(n/2 + 255)/256, 256>>>(Wo, woh, wol, n);
    n = D * FF;    split_bf16<<<(n/2 + 255)/256, 256>>>(W1, w1h, w1l, n);
    n = D * FF;    split_bf16<<<(n/2 + 255)/256, 256>>>(W2, w2h, w2l, n);

    // ---- QKV projections (write bf16 hi/lo directly) ----
    dim3 gProj(D / 128, MTOK / 128);
    gemm_bf16x3<2><<<gProj, 256, SB>>>(xh, xl, wqh, wql, bq, nullptr, qh, ql, MTOK, D, D);
    gemm_bf16x3<2><<<gProj, 256, SB>>>(xh, xl, wkh, wkl, bk, nullptr, kh, kl, MTOK, D, D);
    gemm_bf16x3<2><<<gProj, 256, SB>>>(xh, xl, wvh, wvl, bv, nullptr, vh, vl, MTOK, D, D);

    // ---- tensor-core flash attention ----
    dim3 gAttn(SEQ / 128, NH, BATCH);
    attn_mma<<<gAttn, 256, SA>>>(qh, ql, kh, kl, vh, vl, ctxh, ctxl);

    // ---- O projection ----
    gemm_bf16x3<0><<<gProj, 256, SB>>>(ctxh, ctxl, woh, wol, bo, attn, nullptr, nullptr, MTOK, D, D);

    // ---- LN1 ----
    add_ln<1><<<MTOK, 256>>>(attn, x, ln1g, ln1b, h, hh, hl);

    // ---- FFN ----
    dim3 gFF1(FF / 128, MTOK / 128);
    gemm_bf16x3<1><<<gFF1, 256, SB>>>(hh, hl, w1h, w1l, b1, nullptr, f1h, f1l, MTOK, FF, D);

    dim3 gFF2(D / 128, MTOK / 128);
    gemm_bf16x3<0><<<gFF2, 256, SB>>>(f1h, f1l, w2h, w2l, b2, ff2, nullptr, nullptr, MTOK, D, FF);

    // ---- LN2 ----
    add_ln<0><<<MTOK, 256>>>(ff2, h, ln2g, ln2b, out, nullptr, nullptr);
}

// round 6
// speedup vs baseline: 2.9216x; 1.0886x over previous
#include <cuda_runtime.h>
#include <cuda_bf16.h>
#include <stdint.h>
#include <math.h>

#define D     1024
#define NH    16
#define HD    64
#define FF    4096
#define SEQ   2048
#define BATCH 2
#define MTOK  (BATCH*SEQ)   // 4096 rows
#define D3    (3*D)

// ---------------- scratch (static device globals; no allocs) ----------------
__device__ float g_attnres[MTOK*(size_t)D];
__device__ float g_h[MTOK*(size_t)D];
__device__ float g_ff2[MTOK*(size_t)D];
__device__ float g_bqkv[D3];

__device__ __nv_bfloat16 g_xh[MTOK*(size_t)D],   g_xl[MTOK*(size_t)D];
__device__ __nv_bfloat16 g_qkvh[MTOK*(size_t)D3], g_qkvl[MTOK*(size_t)D3];
__device__ __nv_bfloat16 g_ctxh[MTOK*(size_t)D], g_ctxl[MTOK*(size_t)D];
__device__ __nv_bfloat16 g_hh[MTOK*(size_t)D],   g_hl[MTOK*(size_t)D];
__device__ __nv_bfloat16 g_f1h[MTOK*(size_t)FF], g_f1l[MTOK*(size_t)FF];
__device__ __nv_bfloat16 g_wqkvh[D*(size_t)D3],  g_wqkvl[D*(size_t)D3];
__device__ __nv_bfloat16 g_woh[D*(size_t)D],     g_wol[D*(size_t)D];
__device__ __nv_bfloat16 g_w1h[D*(size_t)FF],    g_w1l[D*(size_t)FF];
__device__ __nv_bfloat16 g_w2h[FF*(size_t)D],    g_w2l[FF*(size_t)D];

// ---------------- helpers --------------------------------------------------
__device__ __forceinline__ unsigned smem_u32(const void* p) {
    return (unsigned)__cvta_generic_to_shared(p);
}
__device__ __forceinline__ void ldsm_x4(unsigned r[4], unsigned addr) {
    asm volatile("ldmatrix.sync.aligned.m8n8.x4.shared.b16 {%0,%1,%2,%3}, [%4];"
                 : "=r"(r[0]), "=r"(r[1]), "=r"(r[2]), "=r"(r[3]) : "r"(addr));
}
__device__ __forceinline__ void ldsm_x4t(unsigned r[4], unsigned addr) {
    asm volatile("ldmatrix.sync.aligned.m8n8.x4.trans.shared.b16 {%0,%1,%2,%3}, [%4];"
                 : "=r"(r[0]), "=r"(r[1]), "=r"(r[2]), "=r"(r[3]) : "r"(addr));
}
__device__ __forceinline__ void ldsm_x2(unsigned r[2], unsigned addr) {
    asm volatile("ldmatrix.sync.aligned.m8n8.x2.shared.b16 {%0,%1}, [%2];"
                 : "=r"(r[0]), "=r"(r[1]) : "r"(addr));
}
__device__ __forceinline__ void ldsm_x2t(unsigned r[2], unsigned addr) {
    asm volatile("ldmatrix.sync.aligned.m8n8.x2.trans.shared.b16 {%0,%1}, [%2];"
                 : "=r"(r[0]), "=r"(r[1]) : "r"(addr));
}
__device__ __forceinline__ void mma_bf16(float c[4], const unsigned a[4], const unsigned b[2]) {
    asm volatile("mma.sync.aligned.m16n8k16.row.col.f32.bf16.bf16.f32 "
                 "{%0,%1,%2,%3}, {%4,%5,%6,%7}, {%8,%9}, {%0,%1,%2,%3};"
                 : "+f"(c[0]), "+f"(c[1]), "+f"(c[2]), "+f"(c[3])
                 : "r"(a[0]), "r"(a[1]), "r"(a[2]), "r"(a[3]), "r"(b[0]), "r"(b[1]));
}
__device__ __forceinline__ void cp16(unsigned dst, const void* src) {
    asm volatile("cp.async.cg.shared.global [%0], [%1], 16;" :: "r"(dst), "l"(src) : "memory");
}
__device__ __forceinline__ void cp_commit() { asm volatile("cp.async.commit_group;" ::: "memory"); }
template <int N>
__device__ __forceinline__ void cp_wait() { asm volatile("cp.async.wait_group %0;" :: "n"(N) : "memory"); }

__device__ __forceinline__ unsigned pack_bf16x2(float a, float b) {
    __nv_bfloat162 p = __floats2bfloat162_rn(a, b);
    return *(unsigned*)&p;
}

// ==================== GEMM: 128x256 block tile, 64x64 warp tile ============
#define ASTR 40    // A row stride (halves): 80B, 80/16=5 (odd) -> conflict-free ldsm
#define BSTR 264   // B row stride (halves): 528B, 528/16=33 (odd)
struct GSmem {
    __nv_bfloat16 Ah[3][128][ASTR];
    __nv_bfloat16 Al[3][128][ASTR];
    __nv_bfloat16 Bh[3][32][BSTR];
    __nv_bfloat16 Bl[3][32][BSTR];
};

// EPI: 0 = fp32 C; 1 = GELU then bf16 hi/lo; 2 = bf16 hi/lo
template <int EPI>
__global__ __launch_bounds__(256, 1) void gemm_bf16x3(
    const __nv_bfloat16* __restrict__ Agh, const __nv_bfloat16* __restrict__ Agl,
    const __nv_bfloat16* __restrict__ Bgh, const __nv_bfloat16* __restrict__ Bgl,
    const float* __restrict__ bias,
    float* __restrict__ C, __nv_bfloat16* __restrict__ Ch, __nv_bfloat16* __restrict__ Cl,
    int M, int N, int K)
{
    extern __shared__ char smem_raw[];
    GSmem& sm = *reinterpret_cast<GSmem*>(smem_raw);

    const int tid  = threadIdx.x;
    const int lane = tid & 31;
    const int wid  = tid >> 5;
    const int warpM = wid & 1;     // 2 warps in M (64 rows each)
    const int warpN = wid >> 1;    // 4 warps in N (64 cols each)
    const int bx = blockIdx.x;     // N tile (256)
    const int by = blockIdx.y;     // M tile (128)
    const int KT = K / 32;

    float acc[4][8][4];
    #pragma unroll
    for (int i = 0; i < 4; i++)
        #pragma unroll
        for (int j = 0; j < 8; j++)
            #pragma unroll
            for (int r = 0; r < 4; r++) acc[i][j][r] = 0.f;

    auto load_stage = [&](int st, int kt) {
        // A: 128 rows x 4 x16B chunks per split
        #pragma unroll
        for (int l = 0; l < 2; l++) {
            int f = tid + l * 256;
            int r = f >> 2, c = (f & 3) * 8;
            const size_t goff = (size_t)(by * 128 + r) * K + kt * 32 + c;
            cp16(smem_u32(&sm.Ah[st][r][c]), Agh + goff);
            cp16(smem_u32(&sm.Al[st][r][c]), Agl + goff);
        }
        // B: 32 rows x 32 x16B chunks per split
        #pragma unroll
        for (int l = 0; l < 4; l++) {
            int f = tid + l * 256;
            int r = f >> 5, c = (f & 31) * 8;
            const size_t goff = (size_t)(kt * 32 + r) * N + bx * 256 + c;
            cp16(smem_u32(&sm.Bh[st][r][c]), Bgh + goff);
            cp16(smem_u32(&sm.Bl[st][r][c]), Bgl + goff);
        }
    };

    load_stage(0, 0); cp_commit();
    load_stage(1, 1); cp_commit();

    const int arow = warpM * 64 + (lane & 15);
    const int acol8 = (lane >> 4) * 8;
    const int brow = ((lane >> 3) & 1) * 8 + (lane & 7);
    const int bcol = warpN * 64 + ((lane >> 4) & 1) * 8;

    for (int kt = 0; kt < KT; kt++) {
        const int st = kt % 3;
        cp_wait<1>();
        __syncthreads();
        if (kt + 2 < KT) load_stage((kt + 2) % 3, kt + 2);
        cp_commit();

        #pragma unroll
        for (int ks = 0; ks < 2; ks++) {
            const int k0 = ks * 16;
            unsigned ah[4][4], al[4][4];
            #pragma unroll
            for (int mi = 0; mi < 4; mi++) {
                ldsm_x4(ah[mi], smem_u32(&sm.Ah[st][arow + mi * 16][k0 + acol8]));
                ldsm_x4(al[mi], smem_u32(&sm.Al[st][arow + mi * 16][k0 + acol8]));
            }
            #pragma unroll
            for (int nn = 0; nn < 4; nn++) {
                unsigned bh[4], bl[4];
                ldsm_x4t(bh, smem_u32(&sm.Bh[st][k0 + brow][bcol + nn * 16]));
                ldsm_x4t(bl, smem_u32(&sm.Bl[st][k0 + brow][bcol + nn * 16]));
                #pragma unroll
                for (int mi = 0; mi < 4; mi++) {
                    mma_bf16(acc[mi][2*nn],   ah[mi], bh);
                    mma_bf16(acc[mi][2*nn],   al[mi], bh);
                    mma_bf16(acc[mi][2*nn],   ah[mi], bl);
                    mma_bf16(acc[mi][2*nn+1], ah[mi], bh + 2);
                    mma_bf16(acc[mi][2*nn+1], al[mi], bh + 2);
                    mma_bf16(acc[mi][2*nn+1], ah[mi], bl + 2);
                }
            }
        }
    }

    // epilogue
    const int g  = lane >> 2;
    const int t2 = (lane & 3) * 2;
    #pragma unroll
    for (int mi = 0; mi < 4; mi++) {
        #pragma unroll
        for (int ni = 0; ni < 8; ni++) {
            int row0 = by * 128 + warpM * 64 + mi * 16 + g;
            int col  = bx * 256 + warpN * 64 + ni * 8 + t2;
            float b0 = bias[col], b1 = bias[col + 1];
            #pragma unroll
            for (int half = 0; half < 2; half++) {
                int row = row0 + half * 8;
                float v0 = acc[mi][ni][half * 2 + 0] + b0;
                float v1 = acc[mi][ni][half * 2 + 1] + b1;
                if (EPI >= 1) {
                    if (EPI == 1) {
                        v0 = 0.5f * v0 * (1.f + erff(v0 * 0.70710678118654752f));
                        v1 = 0.5f * v1 * (1.f + erff(v1 * 0.70710678118654752f));
                    }
                    __nv_bfloat16 h0 = __float2bfloat16_rn(v0);
                    __nv_bfloat16 h1 = __float2bfloat16_rn(v1);
                    __nv_bfloat16 l0 = __float2bfloat16_rn(v0 - __bfloat162float(h0));
                    __nv_bfloat16 l1 = __float2bfloat16_rn(v1 - __bfloat162float(h1));
                    *(__nv_bfloat162*)(Ch + (size_t)row * N + col) = __nv_bfloat162(h0, h1);
                    *(__nv_bfloat162*)(Cl + (size_t)row * N + col) = __nv_bfloat162(l0, l1);
                } else {
                    float2 o; o.x = v0; o.y = v1;
                    *(float2*)(C + (size_t)row * N + col) = o;
                }
            }
        }
    }
}

// ---------------- fp32 -> bf16 hi/lo split (with dst column offset) ---------
__global__ void split_off(const float* __restrict__ src,
                          __nv_bfloat16* __restrict__ hi, __nv_bfloat16* __restrict__ lo,
                          int n, int cols, int ldDst, int colOff)
{
    int i = (blockIdx.x * blockDim.x + threadIdx.x) * 2;
    if (i >= n) return;
    float2 v = *(const float2*)(src + i);
    int r = i / cols, c = i % cols;
    size_t o = (size_t)r * ldDst + colOff + c;
    __nv_bfloat16 h0 = __float2bfloat16_rn(v.x);
    __nv_bfloat16 h1 = __float2bfloat16_rn(v.y);
    __nv_bfloat16 l0 = __float2bfloat16_rn(v.x - __bfloat162float(h0));
    __nv_bfloat16 l1 = __float2bfloat16_rn(v.y - __bfloat162float(h1));
    *(__nv_bfloat162*)(hi + o) = __nv_bfloat162(h0, h1);
    *(__nv_bfloat162*)(lo + o) = __nv_bfloat162(l0, l1);
}

__global__ void concat3(const float* __restrict__ a, const float* __restrict__ b,
                        const float* __restrict__ c, float* __restrict__ dst)
{
    int i = blockIdx.x * 256 + threadIdx.x;
    if (i < D) { dst[i] = a[i]; dst[D + i] = b[i]; dst[2 * D + i] = c[i]; }
}

// ==================== mma.sync flash attention ==============================
#define QPAD 72
struct AttnSmem {
    __nv_bfloat16 Qh[128][QPAD], Ql[128][QPAD];
    __nv_bfloat16 Kh[2][64][QPAD], Kl[2][64][QPAD];
    __nv_bfloat16 Vh[2][64][QPAD], Vl[2][64][QPAD];
};

__global__ __launch_bounds__(256, 1) void attn_mma(
    const __nv_bfloat16* __restrict__ qh, const __nv_bfloat16* __restrict__ ql,
    const __nv_bfloat16* __restrict__ kh, const __nv_bfloat16* __restrict__ kl,
    const __nv_bfloat16* __restrict__ vh, const __nv_bfloat16* __restrict__ vl,
    __nv_bfloat16* __restrict__ ctxh, __nv_bfloat16* __restrict__ ctxl, int ld)
{
    extern __shared__ char smem_raw[];
    AttnSmem& sm = *reinterpret_cast<AttnSmem*>(smem_raw);

    const int tid  = threadIdx.x;
    const int lane = tid & 31;
    const int w    = tid >> 5;
    const int g    = lane >> 2;
    const int t    = lane & 3;

    const int qt = (int)gridDim.x - 1 - (int)blockIdx.x;
    const int h  = blockIdx.y;
    const int b  = blockIdx.z;
    const size_t q0 = (size_t)b * SEQ + qt * 128;
    const int hcol = h * HD;

    #pragma unroll
    for (int l = 0; l < 4; l++) {
        int f = tid + l * 256;
        int r = f >> 3, c = (f & 7) * 8;
        cp16(smem_u32(&sm.Qh[r][c]), qh + (q0 + r) * ld + hcol + c);
        cp16(smem_u32(&sm.Ql[r][c]), ql + (q0 + r) * ld + hcol + c);
    }

    auto load_kv = [&](int st, int kt) {
        const size_t kr0 = (size_t)b * SEQ + kt * 64;
        #pragma unroll
        for (int l = 0; l < 2; l++) {
            int f = tid + l * 256;
            int r = f >> 3, c = (f & 7) * 8;
            const size_t go = (kr0 + r) * ld + hcol + c;
            cp16(smem_u32(&sm.Kh[st][r][c]), kh + go);
            cp16(smem_u32(&sm.Kl[st][r][c]), kl + go);
            cp16(smem_u32(&sm.Vh[st][r][c]), vh + go);
            cp16(smem_u32(&sm.Vl[st][r][c]), vl + go);
        }
    };

    load_kv(0, 0);
    cp_commit();

    const int ktiles = qt * 2 + 2;

    unsigned qfh[4][4], qfl[4][4];
    float m[2] = {-1e30f, -1e30f};
    float lsum[2] = {0.f, 0.f};
    float acc[8][4];
    #pragma unroll
    for (int nf = 0; nf < 8; nf++)
        #pragma unroll
        for (int i = 0; i < 4; i++) acc[nf][i] = 0.f;

    for (int kt = 0; kt < ktiles; kt++) {
        const int st = kt & 1;
        if (kt + 1 < ktiles) { load_kv(st ^ 1, kt + 1); cp_commit(); cp_wait<1>(); }
        else cp_wait<0>();
        __syncthreads();

        if (kt == 0) {
            #pragma unroll
            for (int kf = 0; kf < 4; kf++) {
                int r = w * 16 + (lane & 15);
                int c = kf * 16 + (lane >> 4) * 8;
                ldsm_x4(qfh[kf], smem_u32(&sm.Qh[r][c]));
                ldsm_x4(qfl[kf], smem_u32(&sm.Ql[r][c]));
            }
        }

        float s[8][4];
        #pragma unroll
        for (int nf = 0; nf < 8; nf++)
            #pragma unroll
            for (int i = 0; i < 4; i++) s[nf][i] = 0.f;

        #pragma unroll
        for (int nf = 0; nf < 8; nf++) {
            #pragma unroll
            for (int kf = 0; kf < 4; kf++) {
                unsigned kbh[2], kbl[2];
                int kr = nf * 8 + (lane & 7);
                int kc = kf * 16 + ((lane >> 3) & 1) * 8;
                ldsm_x2(kbh, smem_u32(&sm.Kh[st][kr][kc]));
                ldsm_x2(kbl, smem_u32(&sm.Kl[st][kr][kc]));
                mma_bf16(s[nf], qfh[kf], kbh);
                mma_bf16(s[nf], qfl[kf], kbh);
                mma_bf16(s[nf], qfh[kf], kbl);
            }
        }

        const int kbase = kt * 64;
        const int qbase = qt * 128 + w * 16;
        #pragma unroll
        for (int nf = 0; nf < 8; nf++) {
            #pragma unroll
            for (int i = 0; i < 4; i++) {
                int key = kbase + nf * 8 + 2 * t + (i & 1);
                int qry = qbase + g + (i >> 1) * 8;
                float sv = s[nf][i] * 0.125f;
                s[nf][i] = (key > qry) ? -1e30f : sv;
            }
        }

        float cfac[2];
        #pragma unroll
        for (int r = 0; r < 2; r++) {
            float vmax = -1e30f;
            #pragma unroll
            for (int nf = 0; nf < 8; nf++) {
                vmax = fmaxf(vmax, s[nf][2 * r]);
                vmax = fmaxf(vmax, s[nf][2 * r + 1]);
            }
            vmax = fmaxf(vmax, __shfl_xor_sync(0xffffffffu, vmax, 1));
            vmax = fmaxf(vmax, __shfl_xor_sync(0xffffffffu, vmax, 2));
            float mn = fmaxf(m[r], vmax);
            cfac[r] = __expf(m[r] - mn);
            m[r] = mn;
            float rowsum = 0.f;
            #pragma unroll
            for (int nf = 0; nf < 8; nf++) {
                float p0 = __expf(s[nf][2 * r]     - mn);
                float p1 = __expf(s[nf][2 * r + 1] - mn);
                s[nf][2 * r]     = p0;
                s[nf][2 * r + 1] = p1;
                rowsum += p0 + p1;
            }
            rowsum += __shfl_xor_sync(0xffffffffu, rowsum, 1);
            rowsum += __shfl_xor_sync(0xffffffffu, rowsum, 2);
            lsum[r] = lsum[r] * cfac[r] + rowsum;
        }
        #pragma unroll
        for (int nf = 0; nf < 8; nf++) {
            acc[nf][0] *= cfac[0]; acc[nf][1] *= cfac[0];
            acc[nf][2] *= cfac[1]; acc[nf][3] *= cfac[1];
        }

        unsigned pah[4][4], pal[4][4];
        #pragma unroll
        for (int kf = 0; kf < 4; kf++) {
            #pragma unroll
            for (int half = 0; half < 2; half++) {
                #pragma unroll
                for (int sub = 0; sub < 2; sub++) {
                    int nf = 2 * kf + sub;
                    float p0 = s[nf][2 * half];
                    float p1 = s[nf][2 * half + 1];
                    __nv_bfloat16 h0 = __float2bfloat16_rn(p0);
                    __nv_bfloat16 h1 = __float2bfloat16_rn(p1);
                    float l0 = p0 - __bfloat162float(h0);
                    float l1 = p1 - __bfloat162float(h1);
                    unsigned hp; { __nv_bfloat162 tmp(h0, h1); hp = *(unsigned*)&tmp; }
                    pah[kf][sub * 2 + half] = hp;
                    pal[kf][sub * 2 + half] = pack_bf16x2(l0, l1);
                }
            }
        }

        #pragma unroll
        for (int nf = 0; nf < 8; nf++) {
            #pragma unroll
            for (int kf = 0; kf < 4; kf++) {
                unsigned vb[2], vbl[2];
                int vr = kf * 16 + (lane & 15);
                int vc = nf * 8;
                ldsm_x2t(vb,  smem_u32(&sm.Vh[st][vr][vc]));
                ldsm_x2t(vbl, smem_u32(&sm.Vl[st][vr][vc]));
                mma_bf16(acc[nf], pah[kf], vb);
                mma_bf16(acc[nf], pal[kf], vb);
                mma_bf16(acc[nf], pah[kf], vbl);
            }
        }
        __syncthreads();
    }

    const float inv0 = 1.f / lsum[0];
    const float inv1 = 1.f / lsum[1];
    #pragma unroll
    for (int nf = 0; nf < 8; nf++) {
        int col = hcol + nf * 8 + 2 * t;
        size_t row0 = q0 + w * 16 + g;
        float v0 = acc[nf][0] * inv0, v1 = acc[nf][1] * inv0;
        float v2 = acc[nf][2] * inv1, v3 = acc[nf][3] * inv1;
        __nv_bfloat16 h0 = __float2bfloat16_rn(v0), h1 = __float2bfloat16_rn(v1);
        __nv_bfloat16 h2 = __float2bfloat16_rn(v2), h3 = __float2bfloat16_rn(v3);
        *(__nv_bfloat162*)(ctxh + row0 * D + col) = __nv_bfloat162(h0, h1);
        *(__nv_bfloat162*)(ctxl + row0 * D + col) =
            __nv_bfloat162(__float2bfloat16_rn(v0 - __bfloat162float(h0)),
                           __float2bfloat16_rn(v1 - __bfloat162float(h1)));
        *(__nv_bfloat162*)(ctxh + (row0 + 8) * D + col) = __nv_bfloat162(h2, h3);
        *(__nv_bfloat162*)(ctxl + (row0 + 8) * D + col) =
            __nv_bfloat162(__float2bfloat16_rn(v2 - __bfloat162float(h2)),
                           __float2bfloat16_rn(v3 - __bfloat162float(h3)));
    }
}

// ---------------- fused residual add + LayerNorm ----------------------------
template <int WB>
__global__ __launch_bounds__(256) void add_ln(
    const float* __restrict__ Ain, const float* __restrict__ Bin,
    const float* __restrict__ g, const float* __restrict__ be,
    float* __restrict__ out,
    __nv_bfloat16* __restrict__ oh, __nv_bfloat16* __restrict__ ol)
{
    const int row = blockIdx.x;
    const int tid = threadIdx.x;
    const float* a = Ain + (size_t)row * D;
    const float* b = Bin + (size_t)row * D;

    float vals[D / 256];
    float s = 0.f, s2 = 0.f;
    #pragma unroll
    for (int i = 0; i < D / 256; i++) {
        int idx = tid + i * 256;
        float v = a[idx] + b[idx];
        vals[i] = v;
        s += v;
        s2 += v * v;
    }
    #pragma unroll
    for (int off = 16; off > 0; off >>= 1) {
        s  += __shfl_xor_sync(0xffffffffu, s,  off);
        s2 += __shfl_xor_sync(0xffffffffu, s2, off);
    }
    __shared__ float sh[2][8];
    if ((tid & 31) == 0) { sh[0][tid >> 5] = s; sh[1][tid >> 5] = s2; }
    __syncthreads();
    float ts = 0.f, t2 = 0.f;
    #pragma unroll
    for (int w = 0; w < 8; w++) { ts += sh[0][w]; t2 += sh[1][w]; }

    const float mu  = ts * (1.f / D);
    const float var = t2 * (1.f / D) - mu * mu;
    const float inv = rsqrtf(var + 1e-5f);

    #pragma unroll
    for (int i = 0; i < D / 256; i++) {
        int idx = tid + i * 256;
        float o = (vals[i] - mu) * inv * g[idx] + be[idx];
        out[(size_t)row * D + idx] = o;
        if (WB) {
            __nv_bfloat16 h = __float2bfloat16_rn(o);
            __nv_bfloat16 lo2 = __float2bfloat16_rn(o - __bfloat162float(h));
            oh[(size_t)row * D + idx] = h;
            ol[(size_t)row * D + idx] = lo2;
        }
    }
}

// ---------------- launch -----------------------------------------------------
extern "C" void kernel_launch(void* const* d_in, const int* in_sizes, int n_in,
                              void* d_out, int out_size)
{
    const float* x    = (const float*)d_in[0];
    const float* Wq   = (const float*)d_in[1];
    const float* bq   = (const float*)d_in[2];
    const float* Wk   = (const float*)d_in[3];
    const float* bk   = (const float*)d_in[4];
    const float* Wv   = (const float*)d_in[5];
    const float* bv   = (const float*)d_in[6];
    const float* Wo   = (const float*)d_in[7];
    const float* bo   = (const float*)d_in[8];
    const float* ln1g = (const float*)d_in[9];
    const float* ln1b = (const float*)d_in[10];
    const float* W1   = (const float*)d_in[11];
    const float* b1   = (const float*)d_in[12];
    const float* W2   = (const float*)d_in[13];
    const float* b2   = (const float*)d_in[14];
    const float* ln2g = (const float*)d_in[15];
    const float* ln2b = (const float*)d_in[16];
    float* out = (float*)d_out;

    float *attnres, *h, *ff2, *bqkv;
    cudaGetSymbolAddress((void**)&attnres, g_attnres);
    cudaGetSymbolAddress((void**)&h,    g_h);
    cudaGetSymbolAddress((void**)&ff2,  g_ff2);
    cudaGetSymbolAddress((void**)&bqkv, g_bqkv);

    __nv_bfloat16 *xh,*xl,*qkvh,*qkvl,*ctxh,*ctxl,*hh,*hl,*f1h,*f1l;
    __nv_bfloat16 *wqkvh,*wqkvl,*woh,*wol,*w1h,*w1l,*w2h,*w2l;
    cudaGetSymbolAddress((void**)&xh, g_xh);     cudaGetSymbolAddress((void**)&xl, g_xl);
    cudaGetSymbolAddress((void**)&qkvh, g_qkvh); cudaGetSymbolAddress((void**)&qkvl, g_qkvl);
    cudaGetSymbolAddress((void**)&ctxh, g_ctxh); cudaGetSymbolAddress((void**)&ctxl, g_ctxl);
    cudaGetSymbolAddress((void**)&hh, g_hh);     cudaGetSymbolAddress((void**)&hl, g_hl);
    cudaGetSymbolAddress((void**)&f1h, g_f1h);   cudaGetSymbolAddress((void**)&f1l, g_f1l);
    cudaGetSymbolAddress((void**)&wqkvh, g_wqkvh); cudaGetSymbolAddress((void**)&wqkvl, g_wqkvl);
    cudaGetSymbolAddress((void**)&woh, g_woh);   cudaGetSymbolAddress((void**)&wol, g_wol);
    cudaGetSymbolAddress((void**)&w1h, g_w1h);   cudaGetSymbolAddress((void**)&w1l, g_w1l);
    cudaGetSymbolAddress((void**)&w2h, g_w2h);   cudaGetSymbolAddress((void**)&w2l, g_w2l);

    static int attr_set = 0;
    if (!attr_set) {
        cudaFuncSetAttribute(gemm_bf16x3<0>, cudaFuncAttributeMaxDynamicSharedMemorySize, (int)sizeof(GSmem));
        cudaFuncSetAttribute(gemm_bf16x3<1>, cudaFuncAttributeMaxDynamicSharedMemorySize, (int)sizeof(GSmem));
        cudaFuncSetAttribute(gemm_bf16x3<2>, cudaFuncAttributeMaxDynamicSharedMemorySize, (int)sizeof(GSmem));
        cudaFuncSetAttribute(attn_mma, cudaFuncAttributeMaxDynamicSharedMemorySize, (int)sizeof(AttnSmem));
        attr_set = 1;
    }
    const int SG = (int)sizeof(GSmem);
    const int SA = (int)sizeof(AttnSmem);

    // ---- splits ----
    int n;
    n = MTOK * D; split_off<<<(n/2 + 255)/256, 256>>>(x,  xh,    xl,    n, D,  D,  0);
    n = D * D;    split_off<<<(n/2 + 255)/256, 256>>>(Wq, wqkvh, wqkvl, n, D,  D3, 0);
    n = D * D;    split_off<<<(n/2 + 255)/256, 256>>>(Wk, wqkvh, wqkvl, n, D,  D3, D);
    n = D * D;    split_off<<<(n/2 + 255)/256, 256>>>(Wv, wqkvh, wqkvl, n, D,  D3, 2*D);
    n = D * D;    split_off<<<(n/2 + 255)/256, 256>>>(Wo, woh,   wol,   n, D,  D,  0);
    n = D * FF;   split_off<<<(n/2 + 255)/256, 256>>>(W1, w1h,   w1l,   n, FF, FF, 0);
    n = FF * D;   split_off<<<(n/2 + 255)/256, 256>>>(W2, w2h,   w2l,   n, D,  D,  0);
    concat3<<<(D + 255)/256, 256>>>(bq, bk, bv, bqkv);

    // ---- merged QKV projection (bf16 hi/lo out) ----
    dim3 gQKV(D3 / 256, MTOK / 128);     // (12, 32)
    gemm_bf16x3<2><<<gQKV, 256, SG>>>(xh, xl, wqkvh, wqkvl, bqkv, nullptr, qkvh, qkvl, MTOK, D3, D);

    // ---- flash attention ----
    dim3 gAttn(SEQ / 128, NH, BATCH);
    attn_mma<<<gAttn, 256, SA>>>(qkvh, qkvl, qkvh + D, qkvl + D, qkvh + 2*D, qkvl + 2*D,
                                 ctxh, ctxl, D3);

    // ---- O projection ----
    dim3 gO(D / 256, MTOK / 128);        // (4, 32)
    gemm_bf16x3<0><<<gO, 256, SG>>>(ctxh, ctxl, woh, wol, bo, attnres, nullptr, nullptr, MTOK, D, D);

    // ---- LN1 ----
    add_ln<1><<<MTOK, 256>>>(attnres, x, ln1g, ln1b, h, hh, hl);

    // ---- FFN ----
    dim3 gFF1(FF / 256, MTOK / 128);     // (16, 32)
    gemm_bf16x3<1><<<gFF1, 256, SG>>>(hh, hl, w1h, w1l, b1, nullptr, f1h, f1l, MTOK, FF, D);

    dim3 gFF2(D / 256, MTOK / 128);      // (4, 32)
    gemm_bf16x3<0><<<gFF2, 256, SG>>>(f1h, f1l, w2h, w2l, b2, ff2, nullptr, nullptr, MTOK, D, FF);

    // ---- LN2 ----
    add_ln<0><<<MTOK, 256>>>(ff2, h, ln2g, ln2b, out, nullptr, nullptr);
}

// round 7
// speedup vs baseline: 3.0699x; 1.0507x over previous
#include <cuda_runtime.h>
#include <cuda_bf16.h>
#include <stdint.h>
#include <math.h>

#define D     1024
#define NH    16
#define HD    64
#define FF    4096
#define SEQ   2048
#define BATCH 2
#define MTOK  (BATCH*SEQ)   // 4096 rows
#define D3    (3*D)

// ---------------- scratch (static device globals; no allocs) ----------------
__device__ float g_attnres[MTOK*(size_t)D];
__device__ float g_h[MTOK*(size_t)D];
__device__ float g_ff2[MTOK*(size_t)D];
__device__ float g_bqkv[D3];

__device__ __nv_bfloat16 g_xh[MTOK*(size_t)D],   g_xl[MTOK*(size_t)D];
__device__ __nv_bfloat16 g_qkvh[MTOK*(size_t)D3], g_qkvl[MTOK*(size_t)D3];
__device__ __nv_bfloat16 g_ctxh[MTOK*(size_t)D], g_ctxl[MTOK*(size_t)D];
__device__ __nv_bfloat16 g_hh[MTOK*(size_t)D],   g_hl[MTOK*(size_t)D];
__device__ __nv_bfloat16 g_f1h[MTOK*(size_t)FF], g_f1l[MTOK*(size_t)FF];
__device__ __nv_bfloat16 g_wqkvh[D*(size_t)D3],  g_wqkvl[D*(size_t)D3];
__device__ __nv_bfloat16 g_woh[D*(size_t)D],     g_wol[D*(size_t)D];
__device__ __nv_bfloat16 g_w1h[D*(size_t)FF],    g_w1l[D*(size_t)FF];
__device__ __nv_bfloat16 g_w2h[FF*(size_t)D],    g_w2l[FF*(size_t)D];

// ---------------- helpers --------------------------------------------------
__device__ __forceinline__ unsigned smem_u32(const void* p) {
    return (unsigned)__cvta_generic_to_shared(p);
}
__device__ __forceinline__ void ldsm_x4(unsigned r[4], unsigned addr) {
    asm volatile("ldmatrix.sync.aligned.m8n8.x4.shared.b16 {%0,%1,%2,%3}, [%4];"
                 : "=r"(r[0]), "=r"(r[1]), "=r"(r[2]), "=r"(r[3]) : "r"(addr));
}
__device__ __forceinline__ void ldsm_x4t(unsigned r[4], unsigned addr) {
    asm volatile("ldmatrix.sync.aligned.m8n8.x4.trans.shared.b16 {%0,%1,%2,%3}, [%4];"
                 : "=r"(r[0]), "=r"(r[1]), "=r"(r[2]), "=r"(r[3]) : "r"(addr));
}
__device__ __forceinline__ void ldsm_x2(unsigned r[2], unsigned addr) {
    asm volatile("ldmatrix.sync.aligned.m8n8.x2.shared.b16 {%0,%1}, [%2];"
                 : "=r"(r[0]), "=r"(r[1]) : "r"(addr));
}
__device__ __forceinline__ void ldsm_x2t(unsigned r[2], unsigned addr) {
    asm volatile("ldmatrix.sync.aligned.m8n8.x2.trans.shared.b16 {%0,%1}, [%2];"
                 : "=r"(r[0]), "=r"(r[1]) : "r"(addr));
}
__device__ __forceinline__ void mma_bf16(float c[4], const unsigned a[4], const unsigned b[2]) {
    asm volatile("mma.sync.aligned.m16n8k16.row.col.f32.bf16.bf16.f32 "
                 "{%0,%1,%2,%3}, {%4,%5,%6,%7}, {%8,%9}, {%0,%1,%2,%3};"
                 : "+f"(c[0]), "+f"(c[1]), "+f"(c[2]), "+f"(c[3])
                 : "r"(a[0]), "r"(a[1]), "r"(a[2]), "r"(a[3]), "r"(b[0]), "r"(b[1]));
}
__device__ __forceinline__ void cp16(unsigned dst, const void* src) {
    asm volatile("cp.async.cg.shared.global [%0], [%1], 16;" :: "r"(dst), "l"(src) : "memory");
}
__device__ __forceinline__ void cp_commit() { asm volatile("cp.async.commit_group;" ::: "memory"); }
template <int N>
__device__ __forceinline__ void cp_wait() { asm volatile("cp.async.wait_group %0;" :: "n"(N) : "memory"); }

__device__ __forceinline__ unsigned pack_bf16x2(float a, float b) {
    __nv_bfloat162 p = __floats2bfloat162_rn(a, b);
    return *(unsigned*)&p;
}

// ==================== GEMM: 128x128 block tile, 64x32 warp tile ============
// 3-stage ring, 111KB smem -> 2 CTAs/SM; acc = 64 regs -> <=128 regs/thread.
#define ASTR 40    // A row stride (halves)
#define BSTR 136   // B row stride (halves)
struct GSmem {
    __nv_bfloat16 Ah[3][128][ASTR];
    __nv_bfloat16 Al[3][128][ASTR];
    __nv_bfloat16 Bh[3][32][BSTR];
    __nv_bfloat16 Bl[3][32][BSTR];
};

// EPI: 0 = fp32 C; 1 = GELU then bf16 hi/lo; 2 = bf16 hi/lo
template <int EPI>
__global__ __launch_bounds__(256, 2) void gemm_bf16x3(
    const __nv_bfloat16* __restrict__ Agh, const __nv_bfloat16* __restrict__ Agl,
    const __nv_bfloat16* __restrict__ Bgh, const __nv_bfloat16* __restrict__ Bgl,
    const float* __restrict__ bias,
    float* __restrict__ C, __nv_bfloat16* __restrict__ Ch, __nv_bfloat16* __restrict__ Cl,
    int M, int N, int K)
{
    extern __shared__ char smem_raw[];
    GSmem& sm = *reinterpret_cast<GSmem*>(smem_raw);

    const int tid  = threadIdx.x;
    const int lane = tid & 31;
    const int wid  = tid >> 5;
    const int warpM = wid & 1;     // 2 warps in M (64 rows each)
    const int warpN = wid >> 1;    // 4 warps in N (32 cols each)
    const int bx = blockIdx.x;     // N tile (128)
    const int by = blockIdx.y;     // M tile (128)
    const int KT = K / 32;

    float acc[4][4][4];
    #pragma unroll
    for (int i = 0; i < 4; i++)
        #pragma unroll
        for (int j = 0; j < 4; j++)
            #pragma unroll
            for (int r = 0; r < 4; r++) acc[i][j][r] = 0.f;

    auto load_stage = [&](int st, int kt) {
        // A: 128 rows x 4 x16B chunks per split (512 chunks)
        #pragma unroll
        for (int l = 0; l < 2; l++) {
            int f = tid + l * 256;
            int r = f >> 2, c = (f & 3) * 8;
            const size_t goff = (size_t)(by * 128 + r) * K + kt * 32 + c;
            cp16(smem_u32(&sm.Ah[st][r][c]), Agh + goff);
            cp16(smem_u32(&sm.Al[st][r][c]), Agl + goff);
        }
        // B: 32 rows x 16 x16B chunks per split (512 chunks)
        #pragma unroll
        for (int l = 0; l < 2; l++) {
            int f = tid + l * 256;
            int r = f >> 4, c = (f & 15) * 8;
            const size_t goff = (size_t)(kt * 32 + r) * N + bx * 128 + c;
            cp16(smem_u32(&sm.Bh[st][r][c]), Bgh + goff);
            cp16(smem_u32(&sm.Bl[st][r][c]), Bgl + goff);
        }
    };

    load_stage(0, 0); cp_commit();
    load_stage(1, 1); cp_commit();

    const int arow = warpM * 64 + (lane & 15);
    const int acol8 = (lane >> 4) * 8;
    const int brow = ((lane >> 3) & 1) * 8 + (lane & 7);
    const int bcol = warpN * 32 + ((lane >> 4) & 1) * 8;

    for (int kt = 0; kt < KT; kt++) {
        const int st = kt % 3;
        cp_wait<1>();
        __syncthreads();
        if (kt + 2 < KT) load_stage((kt + 2) % 3, kt + 2);
        cp_commit();

        #pragma unroll
        for (int ks = 0; ks < 2; ks++) {
            const int k0 = ks * 16;
            unsigned ah[4][4], al[4][4];
            #pragma unroll
            for (int mi = 0; mi < 4; mi++) {
                ldsm_x4(ah[mi], smem_u32(&sm.Ah[st][arow + mi * 16][k0 + acol8]));
                ldsm_x4(al[mi], smem_u32(&sm.Al[st][arow + mi * 16][k0 + acol8]));
            }
            #pragma unroll
            for (int nn = 0; nn < 2; nn++) {
                unsigned bh[4], bl[4];
                ldsm_x4t(bh, smem_u32(&sm.Bh[st][k0 + brow][bcol + nn * 16]));
                ldsm_x4t(bl, smem_u32(&sm.Bl[st][k0 + brow][bcol + nn * 16]));
                #pragma unroll
                for (int mi = 0; mi < 4; mi++) {
                    mma_bf16(acc[mi][2*nn],   ah[mi], bh);
                    mma_bf16(acc[mi][2*nn],   al[mi], bh);
                    mma_bf16(acc[mi][2*nn],   ah[mi], bl);
                    mma_bf16(acc[mi][2*nn+1], ah[mi], bh + 2);
                    mma_bf16(acc[mi][2*nn+1], al[mi], bh + 2);
                    mma_bf16(acc[mi][2*nn+1], ah[mi], bl + 2);
                }
            }
        }
    }

    // epilogue
    const int g  = lane >> 2;
    const int t2 = (lane & 3) * 2;
    #pragma unroll
    for (int mi = 0; mi < 4; mi++) {
        #pragma unroll
        for (int ni = 0; ni < 4; ni++) {
            int row0 = by * 128 + warpM * 64 + mi * 16 + g;
            int col  = bx * 128 + warpN * 32 + ni * 8 + t2;
            float b0 = bias[col], b1 = bias[col + 1];
            #pragma unroll
            for (int half = 0; half < 2; half++) {
                int row = row0 + half * 8;
                float v0 = acc[mi][ni][half * 2 + 0] + b0;
                float v1 = acc[mi][ni][half * 2 + 1] + b1;
                if (EPI >= 1) {
                    if (EPI == 1) {
                        v0 = 0.5f * v0 * (1.f + erff(v0 * 0.70710678118654752f));
                        v1 = 0.5f * v1 * (1.f + erff(v1 * 0.70710678118654752f));
                    }
                    __nv_bfloat16 h0 = __float2bfloat16_rn(v0);
                    __nv_bfloat16 h1 = __float2bfloat16_rn(v1);
                    __nv_bfloat16 l0 = __float2bfloat16_rn(v0 - __bfloat162float(h0));
                    __nv_bfloat16 l1 = __float2bfloat16_rn(v1 - __bfloat162float(h1));
                    *(__nv_bfloat162*)(Ch + (size_t)row * N + col) = __nv_bfloat162(h0, h1);
                    *(__nv_bfloat162*)(Cl + (size_t)row * N + col) = __nv_bfloat162(l0, l1);
                } else {
                    float2 o; o.x = v0; o.y = v1;
                    *(float2*)(C + (size_t)row * N + col) = o;
                }
            }
        }
    }
}

// ---------------- fp32 -> bf16 hi/lo split (with dst column offset) ---------
__global__ void split_off(const float* __restrict__ src,
                          __nv_bfloat16* __restrict__ hi, __nv_bfloat16* __restrict__ lo,
                          int n, int cols, int ldDst, int colOff)
{
    int i = (blockIdx.x * blockDim.x + threadIdx.x) * 2;
    if (i >= n) return;
    float2 v = *(const float2*)(src + i);
    int r = i / cols, c = i % cols;
    size_t o = (size_t)r * ldDst + colOff + c;
    __nv_bfloat16 h0 = __float2bfloat16_rn(v.x);
    __nv_bfloat16 h1 = __float2bfloat16_rn(v.y);
    __nv_bfloat16 l0 = __float2bfloat16_rn(v.x - __bfloat162float(h0));
    __nv_bfloat16 l1 = __float2bfloat16_rn(v.y - __bfloat162float(h1));
    *(__nv_bfloat162*)(hi + o) = __nv_bfloat162(h0, h1);
    *(__nv_bfloat162*)(lo + o) = __nv_bfloat162(l0, l1);
}

__global__ void concat3(const float* __restrict__ a, const float* __restrict__ b,
                        const float* __restrict__ c, float* __restrict__ dst)
{
    int i = blockIdx.x * 256 + threadIdx.x;
    if (i < D) { dst[i] = a[i]; dst[D + i] = b[i]; dst[2 * D + i] = c[i]; }
}

// ==================== mma.sync flash attention ==============================
#define QPAD 72
struct AttnSmem {
    __nv_bfloat16 Qh[128][QPAD], Ql[128][QPAD];
    __nv_bfloat16 Kh[2][64][QPAD], Kl[2][64][QPAD];
    __nv_bfloat16 Vh[2][64][QPAD], Vl[2][64][QPAD];
};

__global__ __launch_bounds__(256, 1) void attn_mma(
    const __nv_bfloat16* __restrict__ qh, const __nv_bfloat16* __restrict__ ql,
    const __nv_bfloat16* __restrict__ kh, const __nv_bfloat16* __restrict__ kl,
    const __nv_bfloat16* __restrict__ vh, const __nv_bfloat16* __restrict__ vl,
    __nv_bfloat16* __restrict__ ctxh, __nv_bfloat16* __restrict__ ctxl, int ld)
{
    extern __shared__ char smem_raw[];
    AttnSmem& sm = *reinterpret_cast<AttnSmem*>(smem_raw);

    const int tid  = threadIdx.x;
    const int lane = tid & 31;
    const int w    = tid >> 5;
    const int g    = lane >> 2;
    const int t    = lane & 3;

    const int qt = (int)gridDim.x - 1 - (int)blockIdx.x;
    const int h  = blockIdx.y;
    const int b  = blockIdx.z;
    const size_t q0 = (size_t)b * SEQ + qt * 128;
    const int hcol = h * HD;

    #pragma unroll
    for (int l = 0; l < 4; l++) {
        int f = tid + l * 256;
        int r = f >> 3, c = (f & 7) * 8;
        cp16(smem_u32(&sm.Qh[r][c]), qh + (q0 + r) * ld + hcol + c);
        cp16(smem_u32(&sm.Ql[r][c]), ql + (q0 + r) * ld + hcol + c);
    }

    auto load_kv = [&](int st, int kt) {
        const size_t kr0 = (size_t)b * SEQ + kt * 64;
        #pragma unroll
        for (int l = 0; l < 2; l++) {
            int f = tid + l * 256;
            int r = f >> 3, c = (f & 7) * 8;
            const size_t go = (kr0 + r) * ld + hcol + c;
            cp16(smem_u32(&sm.Kh[st][r][c]), kh + go);
            cp16(smem_u32(&sm.Kl[st][r][c]), kl + go);
            cp16(smem_u32(&sm.Vh[st][r][c]), vh + go);
            cp16(smem_u32(&sm.Vl[st][r][c]), vl + go);
        }
    };

    load_kv(0, 0);
    cp_commit();

    const int ktiles = qt * 2 + 2;

    unsigned qfh[4][4], qfl[4][4];
    float m[2] = {-1e30f, -1e30f};
    float lsum[2] = {0.f, 0.f};
    float acc[8][4];
    #pragma unroll
    for (int nf = 0; nf < 8; nf++)
        #pragma unroll
        for (int i = 0; i < 4; i++) acc[nf][i] = 0.f;

    for (int kt = 0; kt < ktiles; kt++) {
        const int st = kt & 1;
        if (kt + 1 < ktiles) { load_kv(st ^ 1, kt + 1); cp_commit(); cp_wait<1>(); }
        else cp_wait<0>();
        __syncthreads();

        if (kt == 0) {
            #pragma unroll
            for (int kf = 0; kf < 4; kf++) {
                int r = w * 16 + (lane & 15);
                int c = kf * 16 + (lane >> 4) * 8;
                ldsm_x4(qfh[kf], smem_u32(&sm.Qh[r][c]));
                ldsm_x4(qfl[kf], smem_u32(&sm.Ql[r][c]));
            }
        }

        float s[8][4];
        #pragma unroll
        for (int nf = 0; nf < 8; nf++)
            #pragma unroll
            for (int i = 0; i < 4; i++) s[nf][i] = 0.f;

        #pragma unroll
        for (int nf = 0; nf < 8; nf++) {
            #pragma unroll
            for (int kf = 0; kf < 4; kf++) {
                unsigned kbh[2], kbl[2];
                int kr = nf * 8 + (lane & 7);
                int kc = kf * 16 + ((lane >> 3) & 1) * 8;
                ldsm_x2(kbh, smem_u32(&sm.Kh[st][kr][kc]));
                ldsm_x2(kbl, smem_u32(&sm.Kl[st][kr][kc]));
                mma_bf16(s[nf], qfh[kf], kbh);
                mma_bf16(s[nf], qfl[kf], kbh);
                mma_bf16(s[nf], qfh[kf], kbl);
            }
        }

        const int kbase = kt * 64;
        const int qbase = qt * 128 + w * 16;
        #pragma unroll
        for (int nf = 0; nf < 8; nf++) {
            #pragma unroll
            for (int i = 0; i < 4; i++) {
                int key = kbase + nf * 8 + 2 * t + (i & 1);
                int qry = qbase + g + (i >> 1) * 8;
                float sv = s[nf][i] * 0.125f;
                s[nf][i] = (key > qry) ? -1e30f : sv;
            }
        }

        float cfac[2];
        #pragma unroll
        for (int r = 0; r < 2; r++) {
            float vmax = -1e30f;
            #pragma unroll
            for (int nf = 0; nf < 8; nf++) {
                vmax = fmaxf(vmax, s[nf][2 * r]);
                vmax = fmaxf(vmax, s[nf][2 * r + 1]);
            }
            vmax = fmaxf(vmax, __shfl_xor_sync(0xffffffffu, vmax, 1));
            vmax = fmaxf(vmax, __shfl_xor_sync(0xffffffffu, vmax, 2));
            float mn = fmaxf(m[r], vmax);
            cfac[r] = __expf(m[r] - mn);
            m[r] = mn;
            float rowsum = 0.f;
            #pragma unroll
            for (int nf = 0; nf < 8; nf++) {
                float p0 = __expf(s[nf][2 * r]     - mn);
                float p1 = __expf(s[nf][2 * r + 1] - mn);
                s[nf][2 * r]     = p0;
                s[nf][2 * r + 1] = p1;
                rowsum += p0 + p1;
            }
            rowsum += __shfl_xor_sync(0xffffffffu, rowsum, 1);
            rowsum += __shfl_xor_sync(0xffffffffu, rowsum, 2);
            lsum[r] = lsum[r] * cfac[r] + rowsum;
        }
        #pragma unroll
        for (int nf = 0; nf < 8; nf++) {
            acc[nf][0] *= cfac[0]; acc[nf][1] *= cfac[0];
            acc[nf][2] *= cfac[1]; acc[nf][3] *= cfac[1];
        }

        unsigned pah[4][4], pal[4][4];
        #pragma unroll
        for (int kf = 0; kf < 4; kf++) {
            #pragma unroll
            for (int half = 0; half < 2; half++) {
                #pragma unroll
                for (int sub = 0; sub < 2; sub++) {
                    int nf = 2 * kf + sub;
                    float p0 = s[nf][2 * half];
                    float p1 = s[nf][2 * half + 1];
                    __nv_bfloat16 h0 = __float2bfloat16_rn(p0);
                    __nv_bfloat16 h1 = __float2bfloat16_rn(p1);
                    float l0 = p0 - __bfloat162float(h0);
                    float l1 = p1 - __bfloat162float(h1);
                    unsigned hp; { __nv_bfloat162 tmp(h0, h1); hp = *(unsigned*)&tmp; }
                    pah[kf][sub * 2 + half] = hp;
                    pal[kf][sub * 2 + half] = pack_bf16x2(l0, l1);
                }
            }
        }

        #pragma unroll
        for (int nf = 0; nf < 8; nf++) {
            #pragma unroll
            for (int kf = 0; kf < 4; kf++) {
                unsigned vb[2], vbl[2];
                int vr = kf * 16 + (lane & 15);
                int vc = nf * 8;
                ldsm_x2t(vb,  smem_u32(&sm.Vh[st][vr][vc]));
                ldsm_x2t(vbl, smem_u32(&sm.Vl[st][vr][vc]));
                mma_bf16(acc[nf], pah[kf], vb);
                mma_bf16(acc[nf], pal[kf], vb);
                mma_bf16(acc[nf], pah[kf], vbl);
            }
        }
        __syncthreads();
    }

    const float inv0 = 1.f / lsum[0];
    const float inv1 = 1.f / lsum[1];
    #pragma unroll
    for (int nf = 0; nf < 8; nf++) {
        int col = hcol + nf * 8 + 2 * t;
        size_t row0 = q0 + w * 16 + g;
        float v0 = acc[nf][0] * inv0, v1 = acc[nf][1] * inv0;
        float v2 = acc[nf][2] * inv1, v3 = acc[nf][3] * inv1;
        __nv_bfloat16 h0 = __float2bfloat16_rn(v0), h1 = __float2bfloat16_rn(v1);
        __nv_bfloat16 h2 = __float2bfloat16_rn(v2), h3 = __float2bfloat16_rn(v3);
        *(__nv_bfloat162*)(ctxh + row0 * D + col) = __nv_bfloat162(h0, h1);
        *(__nv_bfloat162*)(ctxl + row0 * D + col) =
            __nv_bfloat162(__float2bfloat16_rn(v0 - __bfloat162float(h0)),
                           __float2bfloat16_rn(v1 - __bfloat162float(h1)));
        *(__nv_bfloat162*)(ctxh + (row0 + 8) * D + col) = __nv_bfloat162(h2, h3);
        *(__nv_bfloat162*)(ctxl + (row0 + 8) * D + col) =
            __nv_bfloat162(__float2bfloat16_rn(v2 - __bfloat162float(h2)),
                           __float2bfloat16_rn(v3 - __bfloat162float(h3)));
    }
}

// ---------------- fused residual add + LayerNorm ----------------------------
template <int WB>
__global__ __launch_bounds__(256) void add_ln(
    const float* __restrict__ Ain, const float* __restrict__ Bin,
    const float* __restrict__ g, const float* __restrict__ be,
    float* __restrict__ out,
    __nv_bfloat16* __restrict__ oh, __nv_bfloat16* __restrict__ ol)
{
    const int row = blockIdx.x;
    const int tid = threadIdx.x;
    const float* a = Ain + (size_t)row * D;
    const float* b = Bin + (size_t)row * D;

    float vals[D / 256];
    float s = 0.f, s2 = 0.f;
    #pragma unroll
    for (int i = 0; i < D / 256; i++) {
        int idx = tid + i * 256;
        float v = a[idx] + b[idx];
        vals[i] = v;
        s += v;
        s2 += v * v;
    }
    #pragma unroll
    for (int off = 16; off > 0; off >>= 1) {
        s  += __shfl_xor_sync(0xffffffffu, s,  off);
        s2 += __shfl_xor_sync(0xffffffffu, s2, off);
    }
    __shared__ float sh[2][8];
    if ((tid & 31) == 0) { sh[0][tid >> 5] = s; sh[1][tid >> 5] = s2; }
    __syncthreads();
    float ts = 0.f, t2 = 0.f;
    #pragma unroll
    for (int w = 0; w < 8; w++) { ts += sh[0][w]; t2 += sh[1][w]; }

    const float mu  = ts * (1.f / D);
    const float var = t2 * (1.f / D) - mu * mu;
    const float inv = rsqrtf(var + 1e-5f);

    #pragma unroll
    for (int i = 0; i < D / 256; i++) {
        int idx = tid + i * 256;
        float o = (vals[i] - mu) * inv * g[idx] + be[idx];
        out[(size_t)row * D + idx] = o;
        if (WB) {
            __nv_bfloat16 h = __float2bfloat16_rn(o);
            __nv_bfloat16 lo2 = __float2bfloat16_rn(o - __bfloat162float(h));
            oh[(size_t)row * D + idx] = h;
            ol[(size_t)row * D + idx] = lo2;
        }
    }
}

// ---------------- launch -----------------------------------------------------
extern "C" void kernel_launch(void* const* d_in, const int* in_sizes, int n_in,
                              void* d_out, int out_size)
{
    const float* x    = (const float*)d_in[0];
    const float* Wq   = (const float*)d_in[1];
    const float* bq   = (const float*)d_in[2];
    const float* Wk   = (const float*)d_in[3];
    const float* bk   = (const float*)d_in[4];
    const float* Wv   = (const float*)d_in[5];
    const float* bv   = (const float*)d_in[6];
    const float* Wo   = (const float*)d_in[7];
    const float* bo   = (const float*)d_in[8];
    const float* ln1g = (const float*)d_in[9];
    const float* ln1b = (const float*)d_in[10];
    const float* W1   = (const float*)d_in[11];
    const float* b1   = (const float*)d_in[12];
    const float* W2   = (const float*)d_in[13];
    const float* b2   = (const float*)d_in[14];
    const float* ln2g = (const float*)d_in[15];
    const float* ln2b = (const float*)d_in[16];
    float* out = (float*)d_out;

    float *attnres, *h, *ff2, *bqkv;
    cudaGetSymbolAddress((void**)&attnres, g_attnres);
    cudaGetSymbolAddress((void**)&h,    g_h);
    cudaGetSymbolAddress((void**)&ff2,  g_ff2);
    cudaGetSymbolAddress((void**)&bqkv, g_bqkv);

    __nv_bfloat16 *xh,*xl,*qkvh,*qkvl,*ctxh,*ctxl,*hh,*hl,*f1h,*f1l;
    __nv_bfloat16 *wqkvh,*wqkvl,*woh,*wol,*w1h,*w1l,*w2h,*w2l;
    cudaGetSymbolAddress((void**)&xh, g_xh);     cudaGetSymbolAddress((void**)&xl, g_xl);
    cudaGetSymbolAddress((void**)&qkvh, g_qkvh); cudaGetSymbolAddress((void**)&qkvl, g_qkvl);
    cudaGetSymbolAddress((void**)&ctxh, g_ctxh); cudaGetSymbolAddress((void**)&ctxl, g_ctxl);
    cudaGetSymbolAddress((void**)&hh, g_hh);     cudaGetSymbolAddress((void**)&hl, g_hl);
    cudaGetSymbolAddress((void**)&f1h, g_f1h);   cudaGetSymbolAddress((void**)&f1l, g_f1l);
    cudaGetSymbolAddress((void**)&wqkvh, g_wqkvh); cudaGetSymbolAddress((void**)&wqkvl, g_wqkvl);
    cudaGetSymbolAddress((void**)&woh, g_woh);   cudaGetSymbolAddress((void**)&wol, g_wol);
    cudaGetSymbolAddress((void**)&w1h, g_w1h);   cudaGetSymbolAddress((void**)&w1l, g_w1l);
    cudaGetSymbolAddress((void**)&w2h, g_w2h);   cudaGetSymbolAddress((void**)&w2l, g_w2l);

    static int attr_set = 0;
    if (!attr_set) {
        cudaFuncSetAttribute(gemm_bf16x3<0>, cudaFuncAttributeMaxDynamicSharedMemorySize, (int)sizeof(GSmem));
        cudaFuncSetAttribute(gemm_bf16x3<1>, cudaFuncAttributeMaxDynamicSharedMemorySize, (int)sizeof(GSmem));
        cudaFuncSetAttribute(gemm_bf16x3<2>, cudaFuncAttributeMaxDynamicSharedMemorySize, (int)sizeof(GSmem));
        cudaFuncSetAttribute(attn_mma, cudaFuncAttributeMaxDynamicSharedMemorySize, (int)sizeof(AttnSmem));
        attr_set = 1;
    }
    const int SG = (int)sizeof(GSmem);
    const int SA = (int)sizeof(AttnSmem);

    // ---- splits (ordered so the 6th launch is the QKV GEMM, for ncu -s 5) ----
    int n;
    concat3<<<(D + 255)/256, 256>>>(bq, bk, bv, bqkv);                            // 1
    n = MTOK * D; split_off<<<(n/2 + 255)/256, 256>>>(x,  xh,    xl,    n, D, D,  0);    // 2
    n = D * D;    split_off<<<(n/2 + 255)/256, 256>>>(Wq, wqkvh, wqkvl, n, D, D3, 0);    // 3
    n = D * D;    split_off<<<(n/2 + 255)/256, 256>>>(Wk, wqkvh, wqkvl, n, D, D3, D);    // 4
    n = D * D;    split_off<<<(n/2 + 255)/256, 256>>>(Wv, wqkvh, wqkvl, n, D, D3, 2*D);  // 5

    // ---- merged QKV projection (6th launch) ----
    dim3 gQKV(D3 / 128, MTOK / 128);     // (24, 32)
    gemm_bf16x3<2><<<gQKV, 256, SG>>>(xh, xl, wqkvh, wqkvl, bqkv, nullptr, qkvh, qkvl, MTOK, D3, D);

    // remaining weight splits (independent of QKV output)
    n = D * D;    split_off<<<(n/2 + 255)/256, 256>>>(Wo, woh, wol, n, D,  D,  0);
    n = D * FF;   split_off<<<(n/2 + 255)/256, 256>>>(W1, w1h, w1l, n, FF, FF, 0);
    n = FF * D;   split_off<<<(n/2 + 255)/256, 256>>>(W2, w2h, w2l, n, D,  D,  0);

    // ---- flash attention ----
    dim3 gAttn(SEQ / 128, NH, BATCH);
    attn_mma<<<gAttn, 256, SA>>>(qkvh, qkvl, qkvh + D, qkvl + D, qkvh + 2*D, qkvl + 2*D,
                                 ctxh, ctxl, D3);

    // ---- O projection ----
    dim3 gO(D / 128, MTOK / 128);
    gemm_bf16x3<0><<<gO, 256, SG>>>(ctxh, ctxl, woh, wol, bo, attnres, nullptr, nullptr, MTOK, D, D);

    // ---- LN1 ----
    add_ln<1><<<MTOK, 256>>>(attnres, x, ln1g, ln1b, h, hh, hl);

    // ---- FFN ----
    dim3 gFF1(FF / 128, MTOK / 128);
    gemm_bf16x3<1><<<gFF1, 256, SG>>>(hh, hl, w1h, w1l, b1, nullptr, f1h, f1l, MTOK, FF, D);

    dim3 gFF2(D / 128, MTOK / 128);
    gemm_bf16x3<0><<<gFF2, 256, SG>>>(f1h, f1l, w2h, w2l, b2, ff2, nullptr, nullptr, MTOK, D, FF);

    // ---- LN2 ----
    add_ln<0><<<MTOK, 256>>>(ff2, h, ln2g, ln2b, out, nullptr, nullptr);
}

// round 8
// speedup vs baseline: 6.6923x; 2.1800x over previous
#include <cuda_runtime.h>
#include <cuda_fp16.h>
#include <stdint.h>
#include <math.h>

#define D     1024
#define NH    16
#define HD    64
#define FF    4096
#define SEQ   2048
#define BATCH 2
#define MTOK  (BATCH*SEQ)   // 4096 rows
#define D3    (3*D)

// ---------------- scratch (static device globals; no allocs) ----------------
__device__ float g_attnres[MTOK*(size_t)D];
__device__ float g_h[MTOK*(size_t)D];
__device__ float g_ff2[MTOK*(size_t)D];
__device__ float g_bqkv[D3];

__device__ __half g_x16[MTOK*(size_t)D];
__device__ __half g_qkv16[MTOK*(size_t)D3];
__device__ __half g_ctx16[MTOK*(size_t)D];
__device__ __half g_h16[MTOK*(size_t)D];
__device__ __half g_f116[MTOK*(size_t)FF];
__device__ __half g_wqkv16[D*(size_t)D3];
__device__ __half g_wo16[D*(size_t)D];
__device__ __half g_w116[D*(size_t)FF];
__device__ __half g_w216[FF*(size_t)D];

// ---------------- helpers --------------------------------------------------
__device__ __forceinline__ unsigned smem_u32(const void* p) {
    return (unsigned)__cvta_generic_to_shared(p);
}
__device__ __forceinline__ void ldsm_x4(unsigned r[4], unsigned addr) {
    asm volatile("ldmatrix.sync.aligned.m8n8.x4.shared.b16 {%0,%1,%2,%3}, [%4];"
                 : "=r"(r[0]), "=r"(r[1]), "=r"(r[2]), "=r"(r[3]) : "r"(addr));
}
__device__ __forceinline__ void ldsm_x4t(unsigned r[4], unsigned addr) {
    asm volatile("ldmatrix.sync.aligned.m8n8.x4.trans.shared.b16 {%0,%1,%2,%3}, [%4];"
                 : "=r"(r[0]), "=r"(r[1]), "=r"(r[2]), "=r"(r[3]) : "r"(addr));
}
__device__ __forceinline__ void ldsm_x2(unsigned r[2], unsigned addr) {
    asm volatile("ldmatrix.sync.aligned.m8n8.x2.shared.b16 {%0,%1}, [%2];"
                 : "=r"(r[0]), "=r"(r[1]) : "r"(addr));
}
__device__ __forceinline__ void ldsm_x2t(unsigned r[2], unsigned addr) {
    asm volatile("ldmatrix.sync.aligned.m8n8.x2.trans.shared.b16 {%0,%1}, [%2];"
                 : "=r"(r[0]), "=r"(r[1]) : "r"(addr));
}
__device__ __forceinline__ void mma_f16(float c[4], const unsigned a[4], const unsigned b[2]) {
    asm volatile("mma.sync.aligned.m16n8k16.row.col.f32.f16.f16.f32 "
                 "{%0,%1,%2,%3}, {%4,%5,%6,%7}, {%8,%9}, {%0,%1,%2,%3};"
                 : "+f"(c[0]), "+f"(c[1]), "+f"(c[2]), "+f"(c[3])
                 : "r"(a[0]), "r"(a[1]), "r"(a[2]), "r"(a[3]), "r"(b[0]), "r"(b[1]));
}
__device__ __forceinline__ void cp16(unsigned dst, const void* src) {
    asm volatile("cp.async.cg.shared.global [%0], [%1], 16;" :: "r"(dst), "l"(src) : "memory");
}
__device__ __forceinline__ void cp_commit() { asm volatile("cp.async.commit_group;" ::: "memory"); }
template <int N>
__device__ __forceinline__ void cp_wait() { asm volatile("cp.async.wait_group %0;" :: "n"(N) : "memory"); }

__device__ __forceinline__ unsigned pack_h2(float a, float b) {
    __half2 p = __floats2half2_rn(a, b);
    return *(unsigned*)&p;
}

// ==================== fp16 GEMM: 128x128 block, 64x32 warp tile ============
#define ASTR 40
#define BSTR 136
struct GSmem {
    __half Ah[3][128][ASTR];
    __half Bh[3][32][BSTR];
};

// EPI: 0 = fp32 C; 1 = GELU then fp16; 2 = fp16
template <int EPI>
__global__ __launch_bounds__(256, 2) void gemm_f16(
    const __half* __restrict__ Ag, const __half* __restrict__ Bg,
    const float* __restrict__ bias,
    float* __restrict__ C, __half* __restrict__ Ch,
    int M, int N, int K)
{
    extern __shared__ char smem_raw[];
    GSmem& sm = *reinterpret_cast<GSmem*>(smem_raw);

    const int tid  = threadIdx.x;
    const int lane = tid & 31;
    const int wid  = tid >> 5;
    const int warpM = wid & 1;
    const int warpN = wid >> 1;
    const int bx = blockIdx.x;
    const int by = blockIdx.y;
    const int KT = K / 32;

    float acc[4][4][4];
    #pragma unroll
    for (int i = 0; i < 4; i++)
        #pragma unroll
        for (int j = 0; j < 4; j++)
            #pragma unroll
            for (int r = 0; r < 4; r++) acc[i][j][r] = 0.f;

    auto load_stage = [&](int st, int kt) {
        #pragma unroll
        for (int l = 0; l < 2; l++) {
            int f = tid + l * 256;
            int r = f >> 2, c = (f & 3) * 8;
            cp16(smem_u32(&sm.Ah[st][r][c]), Ag + (size_t)(by * 128 + r) * K + kt * 32 + c);
        }
        #pragma unroll
        for (int l = 0; l < 2; l++) {
            int f = tid + l * 256;
            int r = f >> 4, c = (f & 15) * 8;
            cp16(smem_u32(&sm.Bh[st][r][c]), Bg + (size_t)(kt * 32 + r) * N + bx * 128 + c);
        }
    };

    load_stage(0, 0); cp_commit();
    load_stage(1, 1); cp_commit();

    const int arow = warpM * 64 + (lane & 15);
    const int acol8 = (lane >> 4) * 8;
    const int brow = ((lane >> 3) & 1) * 8 + (lane & 7);
    const int bcol = warpN * 32 + ((lane >> 4) & 1) * 8;

    for (int kt = 0; kt < KT; kt++) {
        const int st = kt % 3;
        cp_wait<1>();
        __syncthreads();
        if (kt + 2 < KT) load_stage((kt + 2) % 3, kt + 2);
        cp_commit();

        #pragma unroll
        for (int ks = 0; ks < 2; ks++) {
            const int k0 = ks * 16;
            unsigned ah[4][4];
            #pragma unroll
            for (int mi = 0; mi < 4; mi++)
                ldsm_x4(ah[mi], smem_u32(&sm.Ah[st][arow + mi * 16][k0 + acol8]));
            #pragma unroll
            for (int nn = 0; nn < 2; nn++) {
                unsigned bh[4];
                ldsm_x4t(bh, smem_u32(&sm.Bh[st][k0 + brow][bcol + nn * 16]));
                #pragma unroll
                for (int mi = 0; mi < 4; mi++) {
                    mma_f16(acc[mi][2*nn],   ah[mi], bh);
                    mma_f16(acc[mi][2*nn+1], ah[mi], bh + 2);
                }
            }
        }
    }

    const int g  = lane >> 2;
    const int t2 = (lane & 3) * 2;
    #pragma unroll
    for (int mi = 0; mi < 4; mi++) {
        #pragma unroll
        for (int ni = 0; ni < 4; ni++) {
            int row0 = by * 128 + warpM * 64 + mi * 16 + g;
            int col  = bx * 128 + warpN * 32 + ni * 8 + t2;
            float b0 = bias[col], b1 = bias[col + 1];
            #pragma unroll
            for (int half = 0; half < 2; half++) {
                int row = row0 + half * 8;
                float v0 = acc[mi][ni][half * 2 + 0] + b0;
                float v1 = acc[mi][ni][half * 2 + 1] + b1;
                if (EPI >= 1) {
                    if (EPI == 1) {
                        v0 = 0.5f * v0 * (1.f + erff(v0 * 0.70710678118654752f));
                        v1 = 0.5f * v1 * (1.f + erff(v1 * 0.70710678118654752f));
                    }
                    *(__half2*)(Ch + (size_t)row * N + col) = __floats2half2_rn(v0, v1);
                } else {
                    float2 o; o.x = v0; o.y = v1;
                    *(float2*)(C + (size_t)row * N + col) = o;
                }
            }
        }
    }
}

// ---------------- fp32 -> fp16 (with dst column offset) ---------------------
__global__ void split_h(const float* __restrict__ src, __half* __restrict__ dst,
                        int n, int cols, int ldDst, int colOff)
{
    int i = (blockIdx.x * blockDim.x + threadIdx.x) * 2;
    if (i >= n) return;
    float2 v = *(const float2*)(src + i);
    int r = i / cols, c = i % cols;
    *(__half2*)(dst + (size_t)r * ldDst + colOff + c) = __floats2half2_rn(v.x, v.y);
}

__global__ void concat3(const float* __restrict__ a, const float* __restrict__ b,
                        const float* __restrict__ c, float* __restrict__ dst)
{
    int i = blockIdx.x * 256 + threadIdx.x;
    if (i < D) { dst[i] = a[i]; dst[D + i] = b[i]; dst[2 * D + i] = c[i]; }
}

// ==================== fp16 mma flash attention ==============================
#define QPAD 72
struct AttnSmem {
    __half Qh[128][QPAD];
    __half Kh[2][64][QPAD];
    __half Vh[2][64][QPAD];
};

__global__ __launch_bounds__(256, 2) void attn_mma(
    const __half* __restrict__ qg, const __half* __restrict__ kg,
    const __half* __restrict__ vg, __half* __restrict__ ctx, int ld)
{
    extern __shared__ char smem_raw[];
    AttnSmem& sm = *reinterpret_cast<AttnSmem*>(smem_raw);

    const int tid  = threadIdx.x;
    const int lane = tid & 31;
    const int w    = tid >> 5;
    const int g    = lane >> 2;
    const int t    = lane & 3;

    const int qt = (int)gridDim.x - 1 - (int)blockIdx.x;
    const int h  = blockIdx.y;
    const int b  = blockIdx.z;
    const size_t q0 = (size_t)b * SEQ + qt * 128;
    const int hcol = h * HD;

    #pragma unroll
    for (int l = 0; l < 4; l++) {
        int f = tid + l * 256;
        int r = f >> 3, c = (f & 7) * 8;
        cp16(smem_u32(&sm.Qh[r][c]), qg + (q0 + r) * ld + hcol + c);
    }

    auto load_kv = [&](int st, int kt) {
        const size_t kr0 = (size_t)b * SEQ + kt * 64;
        #pragma unroll
        for (int l = 0; l < 2; l++) {
            int f = tid + l * 256;
            int r = f >> 3, c = (f & 7) * 8;
            const size_t go = (kr0 + r) * ld + hcol + c;
            cp16(smem_u32(&sm.Kh[st][r][c]), kg + go);
            cp16(smem_u32(&sm.Vh[st][r][c]), vg + go);
        }
    };

    load_kv(0, 0);
    cp_commit();

    const int ktiles = qt * 2 + 2;

    unsigned qf[4][4];
    float m[2] = {-1e30f, -1e30f};
    float lsum[2] = {0.f, 0.f};
    float acc[8][4];
    #pragma unroll
    for (int nf = 0; nf < 8; nf++)
        #pragma unroll
        for (int i = 0; i < 4; i++) acc[nf][i] = 0.f;

    for (int kt = 0; kt < ktiles; kt++) {
        const int st = kt & 1;
        if (kt + 1 < ktiles) { load_kv(st ^ 1, kt + 1); cp_commit(); cp_wait<1>(); }
        else cp_wait<0>();
        __syncthreads();

        if (kt == 0) {
            #pragma unroll
            for (int kf = 0; kf < 4; kf++) {
                int r = w * 16 + (lane & 15);
                int c = kf * 16 + (lane >> 4) * 8;
                ldsm_x4(qf[kf], smem_u32(&sm.Qh[r][c]));
            }
        }

        float s[8][4];
        #pragma unroll
        for (int nf = 0; nf < 8; nf++)
            #pragma unroll
            for (int i = 0; i < 4; i++) s[nf][i] = 0.f;

        #pragma unroll
        for (int nf = 0; nf < 8; nf++) {
            #pragma unroll
            for (int kf = 0; kf < 4; kf++) {
                unsigned kb[2];
                int kr = nf * 8 + (lane & 7);
                int kc = kf * 16 + ((lane >> 3) & 1) * 8;
                ldsm_x2(kb, smem_u32(&sm.Kh[st][kr][kc]));
                mma_f16(s[nf], qf[kf], kb);
            }
        }

        const int kbase = kt * 64;
        const int qbase = qt * 128 + w * 16;
        #pragma unroll
        for (int nf = 0; nf < 8; nf++) {
            #pragma unroll
            for (int i = 0; i < 4; i++) {
                int key = kbase + nf * 8 + 2 * t + (i & 1);
                int qry = qbase + g + (i >> 1) * 8;
                float sv = s[nf][i] * 0.125f;
                s[nf][i] = (key > qry) ? -1e30f : sv;
            }
        }

        float cfac[2];
        #pragma unroll
        for (int r = 0; r < 2; r++) {
            float vmax = -1e30f;
            #pragma unroll
            for (int nf = 0; nf < 8; nf++) {
                vmax = fmaxf(vmax, s[nf][2 * r]);
                vmax = fmaxf(vmax, s[nf][2 * r + 1]);
            }
            vmax = fmaxf(vmax, __shfl_xor_sync(0xffffffffu, vmax, 1));
            vmax = fmaxf(vmax, __shfl_xor_sync(0xffffffffu, vmax, 2));
            float mn = fmaxf(m[r], vmax);
            cfac[r] = __expf(m[r] - mn);
            m[r] = mn;
            float rowsum = 0.f;
            #pragma unroll
            for (int nf = 0; nf < 8; nf++) {
                float p0 = __expf(s[nf][2 * r]     - mn);
                float p1 = __expf(s[nf][2 * r + 1] - mn);
                s[nf][2 * r]     = p0;
                s[nf][2 * r + 1] = p1;
                rowsum += p0 + p1;
            }
            rowsum += __shfl_xor_sync(0xffffffffu, rowsum, 1);
            rowsum += __shfl_xor_sync(0xffffffffu, rowsum, 2);
            lsum[r] = lsum[r] * cfac[r] + rowsum;
        }
        #pragma unroll
        for (int nf = 0; nf < 8; nf++) {
            acc[nf][0] *= cfac[0]; acc[nf][1] *= cfac[0];
            acc[nf][2] *= cfac[1]; acc[nf][3] *= cfac[1];
        }

        unsigned ph[4][4];
        #pragma unroll
        for (int kf = 0; kf < 4; kf++) {
            #pragma unroll
            for (int half = 0; half < 2; half++) {
                #pragma unroll
                for (int sub = 0; sub < 2; sub++) {
                    int nf = 2 * kf + sub;
                    ph[kf][sub * 2 + half] = pack_h2(s[nf][2 * half], s[nf][2 * half + 1]);
                }
            }
        }

        #pragma unroll
        for (int nf = 0; nf < 8; nf++) {
            #pragma unroll
            for (int kf = 0; kf < 4; kf++) {
                unsigned vb[2];
                int vr = kf * 16 + (lane & 15);
                int vc = nf * 8;
                ldsm_x2t(vb, smem_u32(&sm.Vh[st][vr][vc]));
                mma_f16(acc[nf], ph[kf], vb);
            }
        }
        __syncthreads();
    }

    const float inv0 = 1.f / lsum[0];
    const float inv1 = 1.f / lsum[1];
    #pragma unroll
    for (int nf = 0; nf < 8; nf++) {
        int col = hcol + nf * 8 + 2 * t;
        size_t row0 = q0 + w * 16 + g;
        *(__half2*)(ctx + row0 * D + col)       = __floats2half2_rn(acc[nf][0] * inv0, acc[nf][1] * inv0);
        *(__half2*)(ctx + (row0 + 8) * D + col) = __floats2half2_rn(acc[nf][2] * inv1, acc[nf][3] * inv1);
    }
}

// ---------------- fused residual add + LayerNorm ----------------------------
template <int WB>
__global__ __launch_bounds__(256) void add_ln(
    const float* __restrict__ Ain, const float* __restrict__ Bin,
    const float* __restrict__ g, const float* __restrict__ be,
    float* __restrict__ out, __half* __restrict__ oh)
{
    const int row = blockIdx.x;
    const int tid = threadIdx.x;
    const float* a = Ain + (size_t)row * D;
    const float* b = Bin + (size_t)row * D;

    float vals[D / 256];
    float s = 0.f, s2 = 0.f;
    #pragma unroll
    for (int i = 0; i < D / 256; i++) {
        int idx = tid + i * 256;
        float v = a[idx] + b[idx];
        vals[i] = v;
        s += v;
        s2 += v * v;
    }
    #pragma unroll
    for (int off = 16; off > 0; off >>= 1) {
        s  += __shfl_xor_sync(0xffffffffu, s,  off);
        s2 += __shfl_xor_sync(0xffffffffu, s2, off);
    }
    __shared__ float sh[2][8];
    if ((tid & 31) == 0) { sh[0][tid >> 5] = s; sh[1][tid >> 5] = s2; }
    __syncthreads();
    float ts = 0.f, t2 = 0.f;
    #pragma unroll
    for (int w = 0; w < 8; w++) { ts += sh[0][w]; t2 += sh[1][w]; }

    const float mu  = ts * (1.f / D);
    const float var = t2 * (1.f / D) - mu * mu;
    const float inv = rsqrtf(var + 1e-5f);

    #pragma unroll
    for (int i = 0; i < D / 256; i++) {
        int idx = tid + i * 256;
        float o = (vals[i] - mu) * inv * g[idx] + be[idx];
        out[(size_t)row * D + idx] = o;
        if (WB) oh[(size_t)row * D + idx] = __float2half_rn(o);
    }
}

// ---------------- launch -----------------------------------------------------
extern "C" void kernel_launch(void* const* d_in, const int* in_sizes, int n_in,
                              void* d_out, int out_size)
{
    const float* x    = (const float*)d_in[0];
    const float* Wq   = (const float*)d_in[1];
    const float* bq   = (const float*)d_in[2];
    const float* Wk   = (const float*)d_in[3];
    const float* bk   = (const float*)d_in[4];
    const float* Wv   = (const float*)d_in[5];
    const float* bv   = (const float*)d_in[6];
    const float* Wo   = (const float*)d_in[7];
    const float* bo   = (const float*)d_in[8];
    const float* ln1g = (const float*)d_in[9];
    const float* ln1b = (const float*)d_in[10];
    const float* W1   = (const float*)d_in[11];
    const float* b1   = (const float*)d_in[12];
    const float* W2   = (const float*)d_in[13];
    const float* b2   = (const float*)d_in[14];
    const float* ln2g = (const float*)d_in[15];
    const float* ln2b = (const float*)d_in[16];
    float* out = (float*)d_out;

    float *attnres, *h, *ff2, *bqkv;
    cudaGetSymbolAddress((void**)&attnres, g_attnres);
    cudaGetSymbolAddress((void**)&h,    g_h);
    cudaGetSymbolAddress((void**)&ff2,  g_ff2);
    cudaGetSymbolAddress((void**)&bqkv, g_bqkv);

    __half *x16,*qkv16,*ctx16,*h16,*f116,*wqkv16,*wo16,*w116,*w216;
    cudaGetSymbolAddress((void**)&x16,   g_x16);
    cudaGetSymbolAddress((void**)&qkv16, g_qkv16);
    cudaGetSymbolAddress((void**)&ctx16, g_ctx16);
    cudaGetSymbolAddress((void**)&h16,   g_h16);
    cudaGetSymbolAddress((void**)&f116,  g_f116);
    cudaGetSymbolAddress((void**)&wqkv16,g_wqkv16);
    cudaGetSymbolAddress((void**)&wo16,  g_wo16);
    cudaGetSymbolAddress((void**)&w116,  g_w116);
    cudaGetSymbolAddress((void**)&w216,  g_w216);

    static int attr_set = 0;
    if (!attr_set) {
        cudaFuncSetAttribute(gemm_f16<0>, cudaFuncAttributeMaxDynamicSharedMemorySize, (int)sizeof(GSmem));
        cudaFuncSetAttribute(gemm_f16<1>, cudaFuncAttributeMaxDynamicSharedMemorySize, (int)sizeof(GSmem));
        cudaFuncSetAttribute(gemm_f16<2>, cudaFuncAttributeMaxDynamicSharedMemorySize, (int)sizeof(GSmem));
        cudaFuncSetAttribute(attn_mma, cudaFuncAttributeMaxDynamicSharedMemorySize, (int)sizeof(AttnSmem));
        attr_set = 1;
    }
    const int SG = (int)sizeof(GSmem);
    const int SA = (int)sizeof(AttnSmem);

    // ---- conversions (6th launch = QKV GEMM for ncu -s 5) ----
    int n;
    concat3<<<(D + 255)/256, 256>>>(bq, bk, bv, bqkv);                                   // 1
    n = MTOK * D; split_h<<<(n/2 + 255)/256, 256>>>(x,  x16,    n, D, D,  0);            // 2
    n = D * D;    split_h<<<(n/2 + 255)/256, 256>>>(Wq, wqkv16, n, D, D3, 0);            // 3
    n = D * D;    split_h<<<(n/2 + 255)/256, 256>>>(Wk, wqkv16, n, D, D3, D);            // 4
    n = D * D;    split_h<<<(n/2 + 255)/256, 256>>>(Wv, wqkv16, n, D, D3, 2*D);          // 5

    // ---- merged QKV projection (fp16 out) ----
    dim3 gQKV(D3 / 128, MTOK / 128);
    gemm_f16<2><<<gQKV, 256, SG>>>(x16, wqkv16, bqkv, nullptr, qkv16, MTOK, D3, D);      // 6

    n = D * D;    split_h<<<(n/2 + 255)/256, 256>>>(Wo, wo16, n, D,  D,  0);
    n = D * FF;   split_h<<<(n/2 + 255)/256, 256>>>(W1, w116, n, FF, FF, 0);
    n = FF * D;   split_h<<<(n/2 + 255)/256, 256>>>(W2, w216, n, D,  D,  0);

    // ---- flash attention (fp16) ----
    dim3 gAttn(SEQ / 128, NH, BATCH);
    attn_mma<<<gAttn, 256, SA>>>(qkv16, qkv16 + D, qkv16 + 2*D, ctx16, D3);

    // ---- O projection ----
    dim3 gO(D / 128, MTOK / 128);
    gemm_f16<0><<<gO, 256, SG>>>(ctx16, wo16, bo, attnres, nullptr, MTOK, D, D);

    // ---- LN1 ----
    add_ln<1><<<MTOK, 256>>>(attnres, x, ln1g, ln1b, h, h16);

    // ---- FFN ----
    dim3 gFF1(FF / 128, MTOK / 128);
    gemm_f16<1><<<gFF1, 256, SG>>>(h16, w116, b1, nullptr, f116, MTOK, FF, D);

    dim3 gFF2(D / 128, MTOK / 128);
    gemm_f16<0><<<gFF2, 256, SG>>>(f116, w216, b2, ff2, nullptr, MTOK, D, FF);

    // ---- LN2 ----
    add_ln<0><<<MTOK, 256>>>(ff2, h, ln2g, ln2b, out, nullptr);
}

// round 9
// speedup vs baseline: 7.0597x; 1.0549x over previous
#include <cuda_runtime.h>
#include <cuda_fp16.h>
#include <stdint.h>
#include <math.h>

#define D     1024
#define NH    16
#define HD    64
#define FF    4096
#define SEQ   2048
#define BATCH 2
#define MTOK  (BATCH*SEQ)   // 4096 rows
#define D3    (3*D)

// ---------------- scratch (static device globals; no allocs) ----------------
__device__ float g_attnres[MTOK*(size_t)D];
__device__ float g_h[MTOK*(size_t)D];
__device__ float g_ff2[MTOK*(size_t)D];
__device__ float g_bqkv[D3];

__device__ __half g_x16[MTOK*(size_t)D];
__device__ __half g_qkv16[MTOK*(size_t)D3];
__device__ __half g_ctx16[MTOK*(size_t)D];
__device__ __half g_h16[MTOK*(size_t)D];
__device__ __half g_f116[MTOK*(size_t)FF];
__device__ __half g_wqkv16[D*(size_t)D3];
__device__ __half g_wo16[D*(size_t)D];
__device__ __half g_w116[D*(size_t)FF];
__device__ __half g_w216[FF*(size_t)D];

// ---------------- helpers --------------------------------------------------
__device__ __forceinline__ unsigned smem_u32(const void* p) {
    return (unsigned)__cvta_generic_to_shared(p);
}
__device__ __forceinline__ void ldsm_x4(unsigned r[4], unsigned addr) {
    asm volatile("ldmatrix.sync.aligned.m8n8.x4.shared.b16 {%0,%1,%2,%3}, [%4];"
                 : "=r"(r[0]), "=r"(r[1]), "=r"(r[2]), "=r"(r[3]) : "r"(addr));
}
__device__ __forceinline__ void ldsm_x4t(unsigned r[4], unsigned addr) {
    asm volatile("ldmatrix.sync.aligned.m8n8.x4.trans.shared.b16 {%0,%1,%2,%3}, [%4];"
                 : "=r"(r[0]), "=r"(r[1]), "=r"(r[2]), "=r"(r[3]) : "r"(addr));
}
__device__ __forceinline__ void ldsm_x2(unsigned r[2], unsigned addr) {
    asm volatile("ldmatrix.sync.aligned.m8n8.x2.shared.b16 {%0,%1}, [%2];"
                 : "=r"(r[0]), "=r"(r[1]) : "r"(addr));
}
__device__ __forceinline__ void ldsm_x2t(unsigned r[2], unsigned addr) {
    asm volatile("ldmatrix.sync.aligned.m8n8.x2.trans.shared.b16 {%0,%1}, [%2];"
                 : "=r"(r[0]), "=r"(r[1]) : "r"(addr));
}
__device__ __forceinline__ void mma_f16(float c[4], const unsigned a[4], const unsigned b[2]) {
    asm volatile("mma.sync.aligned.m16n8k16.row.col.f32.f16.f16.f32 "
                 "{%0,%1,%2,%3}, {%4,%5,%6,%7}, {%8,%9}, {%0,%1,%2,%3};"
                 : "+f"(c[0]), "+f"(c[1]), "+f"(c[2]), "+f"(c[3])
                 : "r"(a[0]), "r"(a[1]), "r"(a[2]), "r"(a[3]), "r"(b[0]), "r"(b[1]));
}
__device__ __forceinline__ void cp16(unsigned dst, const void* src) {
    asm volatile("cp.async.cg.shared.global [%0], [%1], 16;" :: "r"(dst), "l"(src) : "memory");
}
__device__ __forceinline__ void cp_commit() { asm volatile("cp.async.commit_group;" ::: "memory"); }
template <int N>
__device__ __forceinline__ void cp_wait() { asm volatile("cp.async.wait_group %0;" :: "n"(N) : "memory"); }

__device__ __forceinline__ unsigned pack_h2(float a, float b) {
    __half2 p = __floats2half2_rn(a, b);
    return *(unsigned*)&p;
}

// ==================== fp16 GEMM: 128x128 block, 64x32 warp, BK=64 ==========
#define ASTR 72    // A row stride (halves): 144B -> 9x16B (odd), conflict-free
#define BSTR 136   // B row stride (halves): 272B -> 17x16B (odd)
struct GSmem {
    __half Ah[3][128][ASTR];
    __half Bh[3][64][BSTR];
};

// EPI: 0 = fp32 C; 1 = GELU then fp16; 2 = fp16
template <int EPI>
__global__ __launch_bounds__(256, 2) void gemm_f16(
    const __half* __restrict__ Ag, const __half* __restrict__ Bg,
    const float* __restrict__ bias,
    float* __restrict__ C, __half* __restrict__ Ch,
    int M, int N, int K)
{
    extern __shared__ char smem_raw[];
    GSmem& sm = *reinterpret_cast<GSmem*>(smem_raw);

    const int tid  = threadIdx.x;
    const int lane = tid & 31;
    const int wid  = tid >> 5;
    const int warpM = wid & 1;
    const int warpN = wid >> 1;
    const int bx = blockIdx.x;
    const int by = blockIdx.y;
    const int KT = K / 64;

    float acc[4][4][4];
    #pragma unroll
    for (int i = 0; i < 4; i++)
        #pragma unroll
        for (int j = 0; j < 4; j++)
            #pragma unroll
            for (int r = 0; r < 4; r++) acc[i][j][r] = 0.f;

    auto load_stage = [&](int st, int kt) {
        // A tile: 128 rows x 64 halves = 1024 x16B chunks
        #pragma unroll
        for (int l = 0; l < 4; l++) {
            int f = tid + l * 256;
            int r = f >> 3, c = (f & 7) * 8;
            cp16(smem_u32(&sm.Ah[st][r][c]), Ag + (size_t)(by * 128 + r) * K + kt * 64 + c);
        }
        // B tile: 64 rows x 128 halves = 1024 chunks
        #pragma unroll
        for (int l = 0; l < 4; l++) {
            int f = tid + l * 256;
            int r = f >> 4, c = (f & 15) * 8;
            cp16(smem_u32(&sm.Bh[st][r][c]), Bg + (size_t)(kt * 64 + r) * N + bx * 128 + c);
        }
    };

    load_stage(0, 0); cp_commit();
    load_stage(1, 1); cp_commit();

    const int arow = warpM * 64 + (lane & 15);
    const int acol8 = (lane >> 4) * 8;
    const int brow = ((lane >> 3) & 1) * 8 + (lane & 7);
    const int bcol = warpN * 32 + ((lane >> 4) & 1) * 8;

    for (int kt = 0; kt < KT; kt++) {
        const int st = kt % 3;
        cp_wait<1>();
        __syncthreads();
        if (kt + 2 < KT) load_stage((kt + 2) % 3, kt + 2);
        cp_commit();

        #pragma unroll
        for (int ks = 0; ks < 4; ks++) {
            const int k0 = ks * 16;
            unsigned ah[4][4];
            #pragma unroll
            for (int mi = 0; mi < 4; mi++)
                ldsm_x4(ah[mi], smem_u32(&sm.Ah[st][arow + mi * 16][k0 + acol8]));
            #pragma unroll
            for (int nn = 0; nn < 2; nn++) {
                unsigned bh[4];
                ldsm_x4t(bh, smem_u32(&sm.Bh[st][k0 + brow][bcol + nn * 16]));
                #pragma unroll
                for (int mi = 0; mi < 4; mi++) {
                    mma_f16(acc[mi][2*nn],   ah[mi], bh);
                    mma_f16(acc[mi][2*nn+1], ah[mi], bh + 2);
                }
            }
        }
    }

    const int g  = lane >> 2;
    const int t2 = (lane & 3) * 2;
    #pragma unroll
    for (int mi = 0; mi < 4; mi++) {
        #pragma unroll
        for (int ni = 0; ni < 4; ni++) {
            int row0 = by * 128 + warpM * 64 + mi * 16 + g;
            int col  = bx * 128 + warpN * 32 + ni * 8 + t2;
            float b0 = bias[col], b1 = bias[col + 1];
            #pragma unroll
            for (int half = 0; half < 2; half++) {
                int row = row0 + half * 8;
                float v0 = acc[mi][ni][half * 2 + 0] + b0;
                float v1 = acc[mi][ni][half * 2 + 1] + b1;
                if (EPI >= 1) {
                    if (EPI == 1) {
                        v0 = 0.5f * v0 * (1.f + erff(v0 * 0.70710678118654752f));
                        v1 = 0.5f * v1 * (1.f + erff(v1 * 0.70710678118654752f));
                    }
                    *(__half2*)(Ch + (size_t)row * N + col) = __floats2half2_rn(v0, v1);
                } else {
                    float2 o; o.x = v0; o.y = v1;
                    *(float2*)(C + (size_t)row * N + col) = o;
                }
            }
        }
    }
}

// ---------------- merged fp32 -> fp16 conversion (single launch) ------------
// block regions (each block converts 512 elements):
//  x:[0,8192) Wq:[8192,10240) Wk:[10240,12288) Wv:[12288,14336)
//  Wo:[14336,16384) W1:[16384,24576) W2:[24576,32768)
__global__ __launch_bounds__(256) void convert_all(
    const float* __restrict__ x,  const float* __restrict__ Wq,
    const float* __restrict__ Wk, const float* __restrict__ Wv,
    const float* __restrict__ Wo, const float* __restrict__ W1,
    const float* __restrict__ W2,
    __half* __restrict__ x16, __half* __restrict__ wqkv,
    __half* __restrict__ wo,  __half* __restrict__ w1, __half* __restrict__ w2)
{
    const int bid = blockIdx.x;
    const int tid = threadIdx.x;

    const float* src;
    __half* dst;
    int base;           // block index within region
    int qkvOff = -1;    // >=0: scatter into wqkv with column offset
    if (bid < 8192)       { src = x;  dst = x16; base = bid; }
    else if (bid < 10240) { src = Wq; dst = wqkv; base = bid - 8192;  qkvOff = 0; }
    else if (bid < 12288) { src = Wk; dst = wqkv; base = bid - 10240; qkvOff = D; }
    else if (bid < 14336) { src = Wv; dst = wqkv; base = bid - 12288; qkvOff = 2 * D; }
    else if (bid < 16384) { src = Wo; dst = wo;  base = bid - 14336; }
    else if (bid < 24576) { src = W1; dst = w1;  base = bid - 16384; }
    else                  { src = W2; dst = w2;  base = bid - 24576; }

    int i = (base * 256 + tid) * 2;
    float2 v = *(const float2*)(src + i);
    __half2 hv = __floats2half2_rn(v.x, v.y);
    if (qkvOff >= 0) {
        int r = i >> 10;          // / D
        int c = i & (D - 1);      // % D
        *(__half2*)(dst + (size_t)r * D3 + qkvOff + c) = hv;
    } else {
        *(__half2*)(dst + i) = hv;
    }
}

__global__ void concat3(const float* __restrict__ a, const float* __restrict__ b,
                        const float* __restrict__ c, float* __restrict__ dst)
{
    int i = blockIdx.x * 256 + threadIdx.x;
    if (i < D) { dst[i] = a[i]; dst[D + i] = b[i]; dst[2 * D + i] = c[i]; }
}

// ==================== fp16 mma flash attention (exp2 softmax) ===============
#define QPAD 72
struct AttnSmem {
    __half Qh[128][QPAD];
    __half Kh[2][64][QPAD];
    __half Vh[2][64][QPAD];
};

__global__ __launch_bounds__(256, 2) void attn_mma(
    const __half* __restrict__ qg, const __half* __restrict__ kg,
    const __half* __restrict__ vg, __half* __restrict__ ctx, int ld)
{
    extern __shared__ char smem_raw[];
    AttnSmem& sm = *reinterpret_cast<AttnSmem*>(smem_raw);

    const int tid  = threadIdx.x;
    const int lane = tid & 31;
    const int w    = tid >> 5;
    const int g    = lane >> 2;
    const int t    = lane & 3;

    const int qt = (int)gridDim.x - 1 - (int)blockIdx.x;
    const int h  = blockIdx.y;
    const int b  = blockIdx.z;
    const size_t q0 = (size_t)b * SEQ + qt * 128;
    const int hcol = h * HD;
    const float SC = 0.125f * 1.44269504088896340736f;   // scale * log2(e)

    #pragma unroll
    for (int l = 0; l < 4; l++) {
        int f = tid + l * 256;
        int r = f >> 3, c = (f & 7) * 8;
        cp16(smem_u32(&sm.Qh[r][c]), qg + (q0 + r) * ld + hcol + c);
    }

    auto load_kv = [&](int st, int kt) {
        const size_t kr0 = (size_t)b * SEQ + kt * 64;
        #pragma unroll
        for (int l = 0; l < 2; l++) {
            int f = tid + l * 256;
            int r = f >> 3, c = (f & 7) * 8;
            const size_t go = (kr0 + r) * ld + hcol + c;
            cp16(smem_u32(&sm.Kh[st][r][c]), kg + go);
            cp16(smem_u32(&sm.Vh[st][r][c]), vg + go);
        }
    };

    load_kv(0, 0);
    cp_commit();

    const int ktiles = qt * 2 + 2;

    unsigned qf[4][4];
    float m[2] = {-1e30f, -1e30f};
    float lsum[2] = {0.f, 0.f};
    float acc[8][4];
    #pragma unroll
    for (int nf = 0; nf < 8; nf++)
        #pragma unroll
        for (int i = 0; i < 4; i++) acc[nf][i] = 0.f;

    for (int kt = 0; kt < ktiles; kt++) {
        const int st = kt & 1;
        if (kt + 1 < ktiles) { load_kv(st ^ 1, kt + 1); cp_commit(); cp_wait<1>(); }
        else cp_wait<0>();
        __syncthreads();

        if (kt == 0) {
            #pragma unroll
            for (int kf = 0; kf < 4; kf++) {
                int r = w * 16 + (lane & 15);
                int c = kf * 16 + (lane >> 4) * 8;
                ldsm_x4(qf[kf], smem_u32(&sm.Qh[r][c]));
            }
        }

        float s[8][4];
        #pragma unroll
        for (int nf = 0; nf < 8; nf++)
            #pragma unroll
            for (int i = 0; i < 4; i++) s[nf][i] = 0.f;

        #pragma unroll
        for (int nf = 0; nf < 8; nf++) {
            #pragma unroll
            for (int kf = 0; kf < 4; kf++) {
                unsigned kb[2];
                int kr = nf * 8 + (lane & 7);
                int kc = kf * 16 + ((lane >> 3) & 1) * 8;
                ldsm_x2(kb, smem_u32(&sm.Kh[st][kr][kc]));
                mma_f16(s[nf], qf[kf], kb);
            }
        }

        // scale into log2 domain + causal mask
        const int kbase = kt * 64;
        const int qbase = qt * 128 + w * 16;
        #pragma unroll
        for (int nf = 0; nf < 8; nf++) {
            #pragma unroll
            for (int i = 0; i < 4; i++) {
                int key = kbase + nf * 8 + 2 * t + (i & 1);
                int qry = qbase + g + (i >> 1) * 8;
                float sv = s[nf][i] * SC;
                s[nf][i] = (key > qry) ? -1e30f : sv;
            }
        }

        float cfac[2];
        #pragma unroll
        for (int r = 0; r < 2; r++) {
            float vmax = -1e30f;
            #pragma unroll
            for (int nf = 0; nf < 8; nf++) {
                vmax = fmaxf(vmax, s[nf][2 * r]);
                vmax = fmaxf(vmax, s[nf][2 * r + 1]);
            }
            vmax = fmaxf(vmax, __shfl_xor_sync(0xffffffffu, vmax, 1));
            vmax = fmaxf(vmax, __shfl_xor_sync(0xffffffffu, vmax, 2));
            float mn = fmaxf(m[r], vmax);
            cfac[r] = exp2f(m[r] - mn);
            m[r] = mn;
            float rowsum = 0.f;
            #pragma unroll
            for (int nf = 0; nf < 8; nf++) {
                float p0 = exp2f(s[nf][2 * r]     - mn);
                float p1 = exp2f(s[nf][2 * r + 1] - mn);
                s[nf][2 * r]     = p0;
                s[nf][2 * r + 1] = p1;
                rowsum += p0 + p1;
            }
            rowsum += __shfl_xor_sync(0xffffffffu, rowsum, 1);
            rowsum += __shfl_xor_sync(0xffffffffu, rowsum, 2);
            lsum[r] = lsum[r] * cfac[r] + rowsum;
        }
        #pragma unroll
        for (int nf = 0; nf < 8; nf++) {
            acc[nf][0] *= cfac[0]; acc[nf][1] *= cfac[0];
            acc[nf][2] *= cfac[1]; acc[nf][3] *= cfac[1];
        }

        unsigned ph[4][4];
        #pragma unroll
        for (int kf = 0; kf < 4; kf++) {
            #pragma unroll
            for (int half = 0; half < 2; half++) {
                #pragma unroll
                for (int sub = 0; sub < 2; sub++) {
                    int nf = 2 * kf + sub;
                    ph[kf][sub * 2 + half] = pack_h2(s[nf][2 * half], s[nf][2 * half + 1]);
                }
            }
        }

        #pragma unroll
        for (int nf = 0; nf < 8; nf++) {
            #pragma unroll
            for (int kf = 0; kf < 4; kf++) {
                unsigned vb[2];
                int vr = kf * 16 + (lane & 15);
                int vc = nf * 8;
                ldsm_x2t(vb, smem_u32(&sm.Vh[st][vr][vc]));
                mma_f16(acc[nf], ph[kf], vb);
            }
        }
        __syncthreads();
    }

    const float inv0 = 1.f / lsum[0];
    const float inv1 = 1.f / lsum[1];
    #pragma unroll
    for (int nf = 0; nf < 8; nf++) {
        int col = hcol + nf * 8 + 2 * t;
        size_t row0 = q0 + w * 16 + g;
        *(__half2*)(ctx + row0 * D + col)       = __floats2half2_rn(acc[nf][0] * inv0, acc[nf][1] * inv0);
        *(__half2*)(ctx + (row0 + 8) * D + col) = __floats2half2_rn(acc[nf][2] * inv1, acc[nf][3] * inv1);
    }
}

// ---------------- fused residual add + LayerNorm ----------------------------
template <int WB>
__global__ __launch_bounds__(256) void add_ln(
    const float* __restrict__ Ain, const float* __restrict__ Bin,
    const float* __restrict__ g, const float* __restrict__ be,
    float* __restrict__ out, __half* __restrict__ oh)
{
    const int row = blockIdx.x;
    const int tid = threadIdx.x;
    const float* a = Ain + (size_t)row * D;
    const float* b = Bin + (size_t)row * D;

    float vals[D / 256];
    float s = 0.f, s2 = 0.f;
    #pragma unroll
    for (int i = 0; i < D / 256; i++) {
        int idx = tid + i * 256;
        float v = a[idx] + b[idx];
        vals[i] = v;
        s += v;
        s2 += v * v;
    }
    #pragma unroll
    for (int off = 16; off > 0; off >>= 1) {
        s  += __shfl_xor_sync(0xffffffffu, s,  off);
        s2 += __shfl_xor_sync(0xffffffffu, s2, off);
    }
    __shared__ float sh[2][8];
    if ((tid & 31) == 0) { sh[0][tid >> 5] = s; sh[1][tid >> 5] = s2; }
    __syncthreads();
    float ts = 0.f, t2 = 0.f;
    #pragma unroll
    for (int w = 0; w < 8; w++) { ts += sh[0][w]; t2 += sh[1][w]; }

    const float mu  = ts * (1.f / D);
    const float var = t2 * (1.f / D) - mu * mu;
    const float inv = rsqrtf(var + 1e-5f);

    #pragma unroll
    for (int i = 0; i < D / 256; i++) {
        int idx = tid + i * 256;
        float o = (vals[i] - mu) * inv * g[idx] + be[idx];
        out[(size_t)row * D + idx] = o;
        if (WB) oh[(size_t)row * D + idx] = __float2half_rn(o);
    }
}

// ---------------- launch -----------------------------------------------------
extern "C" void kernel_launch(void* const* d_in, const int* in_sizes, int n_in,
                              void* d_out, int out_size)
{
    const float* x    = (const float*)d_in[0];
    const float* Wq   = (const float*)d_in[1];
    const float* bq   = (const float*)d_in[2];
    const float* Wk   = (const float*)d_in[3];
    const float* bk   = (const float*)d_in[4];
    const float* Wv   = (const float*)d_in[5];
    const float* bv   = (const float*)d_in[6];
    const float* Wo   = (const float*)d_in[7];
    const float* bo   = (const float*)d_in[8];
    const float* ln1g = (const float*)d_in[9];
    const float* ln1b = (const float*)d_in[10];
    const float* W1   = (const float*)d_in[11];
    const float* b1   = (const float*)d_in[12];
    const float* W2   = (const float*)d_in[13];
    const float* b2   = (const float*)d_in[14];
    const float* ln2g = (const float*)d_in[15];
    const float* ln2b = (const float*)d_in[16];
    float* out = (float*)d_out;

    float *attnres, *h, *ff2, *bqkv;
    cudaGetSymbolAddress((void**)&attnres, g_attnres);
    cudaGetSymbolAddress((void**)&h,    g_h);
    cudaGetSymbolAddress((void**)&ff2,  g_ff2);
    cudaGetSymbolAddress((void**)&bqkv, g_bqkv);

    __half *x16,*qkv16,*ctx16,*h16,*f116,*wqkv16,*wo16,*w116,*w216;
    cudaGetSymbolAddress((void**)&x16,   g_x16);
    cudaGetSymbolAddress((void**)&qkv16, g_qkv16);
    cudaGetSymbolAddress((void**)&ctx16, g_ctx16);
    cudaGetSymbolAddress((void**)&h16,   g_h16);
    cudaGetSymbolAddress((void**)&f116,  g_f116);
    cudaGetSymbolAddress((void**)&wqkv16,g_wqkv16);
    cudaGetSymbolAddress((void**)&wo16,  g_wo16);
    cudaGetSymbolAddress((void**)&w116,  g_w116);
    cudaGetSymbolAddress((void**)&w216,  g_w216);

    static int attr_set = 0;
    if (!attr_set) {
        cudaFuncSetAttribute(gemm_f16<0>, cudaFuncAttributeMaxDynamicSharedMemorySize, (int)sizeof(GSmem));
        cudaFuncSetAttribute(gemm_f16<1>, cudaFuncAttributeMaxDynamicSharedMemorySize, (int)sizeof(GSmem));
        cudaFuncSetAttribute(gemm_f16<2>, cudaFuncAttributeMaxDynamicSharedMemorySize, (int)sizeof(GSmem));
        cudaFuncSetAttribute(attn_mma, cudaFuncAttributeMaxDynamicSharedMemorySize, (int)sizeof(AttnSmem));
        attr_set = 1;
    }
    const int SG = (int)sizeof(GSmem);
    const int SA = (int)sizeof(AttnSmem);

    // ---- conversions: 2 launches total ----
    concat3<<<(D + 255)/256, 256>>>(bq, bk, bv, bqkv);
    convert_all<<<32768, 256>>>(x, Wq, Wk, Wv, Wo, W1, W2,
                                x16, wqkv16, wo16, w116, w216);

    // ---- merged QKV projection (fp16 out) ----
    dim3 gQKV(D3 / 128, MTOK / 128);
    gemm_f16<2><<<gQKV, 256, SG>>>(x16, wqkv16, bqkv, nullptr, qkv16, MTOK, D3, D);

    // ---- flash attention (fp16) ----
    dim3 gAttn(SEQ / 128, NH, BATCH);
    attn_mma<<<gAttn, 256, SA>>>(qkv16, qkv16 + D, qkv16 + 2*D, ctx16, D3);

    // ---- O projection ----
    dim3 gO(D / 128, MTOK / 128);
    gemm_f16<0><<<gO, 256, SG>>>(ctx16, wo16, bo, attnres, nullptr, MTOK, D, D);

    // ---- LN1 ----
    add_ln<1><<<MTOK, 256>>>(attnres, x, ln1g, ln1b, h, h16);

    // ---- FFN ----
    dim3 gFF1(FF / 128, MTOK / 128);
    gemm_f16<1><<<gFF1, 256, SG>>>(h16, w116, b1, nullptr, f116, MTOK, FF, D);

    dim3 gFF2(D / 128, MTOK / 128);
    gemm_f16<0><<<gFF2, 256, SG>>>(f116, w216, b2, ff2, nullptr, MTOK, D, FF);

    // ---- LN2 ----
    add_ln<0><<<MTOK, 256>>>(ff2, h, ln2g, ln2b, out, nullptr);
}

// round 10
// speedup vs baseline: 7.1484x; 1.0126x over previous
#include <cuda_runtime.h>
#include <cuda_fp16.h>
#include <stdint.h>
#include <math.h>

#define D     1024
#define NH    16
#define HD    64
#define FF    4096
#define SEQ   2048
#define BATCH 2
#define MTOK  (BATCH*SEQ)   // 4096 rows
#define D3    (3*D)

// ---------------- scratch (static device globals; no allocs) ----------------
__device__ float g_attnres[MTOK*(size_t)D];
__device__ float g_h[MTOK*(size_t)D];
__device__ float g_ff2[MTOK*(size_t)D];
__device__ float g_bqkv[D3];

__device__ __half g_x16[MTOK*(size_t)D];
__device__ __half g_qkv16[MTOK*(size_t)D3];
__device__ __half g_ctx16[MTOK*(size_t)D];
__device__ __half g_h16[MTOK*(size_t)D];
__device__ __half g_f116[MTOK*(size_t)FF];
__device__ __half g_wqkv16[D*(size_t)D3];
__device__ __half g_wo16[D*(size_t)D];
__device__ __half g_w116[D*(size_t)FF];
__device__ __half g_w216[FF*(size_t)D];

// ---------------- helpers --------------------------------------------------
__device__ __forceinline__ unsigned smem_u32(const void* p) {
    return (unsigned)__cvta_generic_to_shared(p);
}
__device__ __forceinline__ void ldsm_x4(unsigned r[4], unsigned addr) {
    asm volatile("ldmatrix.sync.aligned.m8n8.x4.shared.b16 {%0,%1,%2,%3}, [%4];"
                 : "=r"(r[0]), "=r"(r[1]), "=r"(r[2]), "=r"(r[3]) : "r"(addr));
}
__device__ __forceinline__ void ldsm_x4t(unsigned r[4], unsigned addr) {
    asm volatile("ldmatrix.sync.aligned.m8n8.x4.trans.shared.b16 {%0,%1,%2,%3}, [%4];"
                 : "=r"(r[0]), "=r"(r[1]), "=r"(r[2]), "=r"(r[3]) : "r"(addr));
}
__device__ __forceinline__ void mma_f16(float c[4], const unsigned a[4], const unsigned b[2]) {
    asm volatile("mma.sync.aligned.m16n8k16.row.col.f32.f16.f16.f32 "
                 "{%0,%1,%2,%3}, {%4,%5,%6,%7}, {%8,%9}, {%0,%1,%2,%3};"
                 : "+f"(c[0]), "+f"(c[1]), "+f"(c[2]), "+f"(c[3])
                 : "r"(a[0]), "r"(a[1]), "r"(a[2]), "r"(a[3]), "r"(b[0]), "r"(b[1]));
}
__device__ __forceinline__ void cp16(unsigned dst, const void* src) {
    asm volatile("cp.async.cg.shared.global [%0], [%1], 16;" :: "r"(dst), "l"(src) : "memory");
}
__device__ __forceinline__ void cp_commit() { asm volatile("cp.async.commit_group;" ::: "memory"); }
template <int N>
__device__ __forceinline__ void cp_wait() { asm volatile("cp.async.wait_group %0;" :: "n"(N) : "memory"); }

__device__ __forceinline__ unsigned pack_h2(float a, float b) {
    __half2 p = __floats2half2_rn(a, b);
    return *(unsigned*)&p;
}

// ==================== fp16 GEMM: 128x128 block, 64x32 warp, BK=64 ==========
#define ASTR 72
#define BSTR 136
struct GSmem {
    __half Ah[3][128][ASTR];
    __half Bh[3][64][BSTR];
};

// EPI: 0 = fp32 C; 1 = GELU then fp16; 2 = fp16
template <int EPI>
__global__ __launch_bounds__(256, 2) void gemm_f16(
    const __half* __restrict__ Ag, const __half* __restrict__ Bg,
    const float* __restrict__ bias,
    float* __restrict__ C, __half* __restrict__ Ch,
    int M, int N, int K)
{
    extern __shared__ char smem_raw[];
    GSmem& sm = *reinterpret_cast<GSmem*>(smem_raw);

    const int tid  = threadIdx.x;
    const int lane = tid & 31;
    const int wid  = tid >> 5;
    const int warpM = wid & 1;
    const int warpN = wid >> 1;
    const int bx = blockIdx.x;
    const int by = blockIdx.y;
    const int KT = K / 64;

    float acc[4][4][4];
    #pragma unroll
    for (int i = 0; i < 4; i++)
        #pragma unroll
        for (int j = 0; j < 4; j++)
            #pragma unroll
            for (int r = 0; r < 4; r++) acc[i][j][r] = 0.f;

    auto load_stage = [&](int st, int kt) {
        #pragma unroll
        for (int l = 0; l < 4; l++) {
            int f = tid + l * 256;
            int r = f >> 3, c = (f & 7) * 8;
            cp16(smem_u32(&sm.Ah[st][r][c]), Ag + (size_t)(by * 128 + r) * K + kt * 64 + c);
        }
        #pragma unroll
        for (int l = 0; l < 4; l++) {
            int f = tid + l * 256;
            int r = f >> 4, c = (f & 15) * 8;
            cp16(smem_u32(&sm.Bh[st][r][c]), Bg + (size_t)(kt * 64 + r) * N + bx * 128 + c);
        }
    };

    load_stage(0, 0); cp_commit();
    load_stage(1, 1); cp_commit();

    const int arow = warpM * 64 + (lane & 15);
    const int acol8 = (lane >> 4) * 8;
    const int brow = ((lane >> 3) & 1) * 8 + (lane & 7);
    const int bcol = warpN * 32 + ((lane >> 4) & 1) * 8;

    for (int kt = 0; kt < KT; kt++) {
        const int st = kt % 3;
        cp_wait<1>();
        __syncthreads();
        if (kt + 2 < KT) load_stage((kt + 2) % 3, kt + 2);
        cp_commit();

        #pragma unroll
        for (int ks = 0; ks < 4; ks++) {
            const int k0 = ks * 16;
            unsigned ah[4][4];
            #pragma unroll
            for (int mi = 0; mi < 4; mi++)
                ldsm_x4(ah[mi], smem_u32(&sm.Ah[st][arow + mi * 16][k0 + acol8]));
            #pragma unroll
            for (int nn = 0; nn < 2; nn++) {
                unsigned bh[4];
                ldsm_x4t(bh, smem_u32(&sm.Bh[st][k0 + brow][bcol + nn * 16]));
                #pragma unroll
                for (int mi = 0; mi < 4; mi++) {
                    mma_f16(acc[mi][2*nn],   ah[mi], bh);
                    mma_f16(acc[mi][2*nn+1], ah[mi], bh + 2);
                }
            }
        }
    }

    const int g  = lane >> 2;
    const int t2 = (lane & 3) * 2;
    #pragma unroll
    for (int mi = 0; mi < 4; mi++) {
        #pragma unroll
        for (int ni = 0; ni < 4; ni++) {
            int row0 = by * 128 + warpM * 64 + mi * 16 + g;
            int col  = bx * 128 + warpN * 32 + ni * 8 + t2;
            float b0 = bias[col], b1 = bias[col + 1];
            #pragma unroll
            for (int half = 0; half < 2; half++) {
                int row = row0 + half * 8;
                float v0 = acc[mi][ni][half * 2 + 0] + b0;
                float v1 = acc[mi][ni][half * 2 + 1] + b1;
                if (EPI >= 1) {
                    if (EPI == 1) {
                        v0 = 0.5f * v0 * (1.f + erff(v0 * 0.70710678118654752f));
                        v1 = 0.5f * v1 * (1.f + erff(v1 * 0.70710678118654752f));
                    }
                    *(__half2*)(Ch + (size_t)row * N + col) = __floats2half2_rn(v0, v1);
                } else {
                    float2 o; o.x = v0; o.y = v1;
                    *(float2*)(C + (size_t)row * N + col) = o;
                }
            }
        }
    }
}

// ---------------- merged fp32 -> fp16 conversion (single launch) ------------
__global__ __launch_bounds__(256) void convert_all(
    const float* __restrict__ x,  const float* __restrict__ Wq,
    const float* __restrict__ Wk, const float* __restrict__ Wv,
    const float* __restrict__ Wo, const float* __restrict__ W1,
    const float* __restrict__ W2,
    __half* __restrict__ x16, __half* __restrict__ wqkv,
    __half* __restrict__ wo,  __half* __restrict__ w1, __half* __restrict__ w2)
{
    const int bid = blockIdx.x;
    const int tid = threadIdx.x;

    const float* src;
    __half* dst;
    int base;
    int qkvOff = -1;
    if (bid < 8192)       { src = x;  dst = x16; base = bid; }
    else if (bid < 10240) { src = Wq; dst = wqkv; base = bid - 8192;  qkvOff = 0; }
    else if (bid < 12288) { src = Wk; dst = wqkv; base = bid - 10240; qkvOff = D; }
    else if (bid < 14336) { src = Wv; dst = wqkv; base = bid - 12288; qkvOff = 2 * D; }
    else if (bid < 16384) { src = Wo; dst = wo;  base = bid - 14336; }
    else if (bid < 24576) { src = W1; dst = w1;  base = bid - 16384; }
    else                  { src = W2; dst = w2;  base = bid - 24576; }

    int i = (base * 256 + tid) * 2;
    float2 v = *(const float2*)(src + i);
    __half2 hv = __floats2half2_rn(v.x, v.y);
    if (qkvOff >= 0) {
        int r = i >> 10;
        int c = i & (D - 1);
        *(__half2*)(dst + (size_t)r * D3 + qkvOff + c) = hv;
    } else {
        *(__half2*)(dst + i) = hv;
    }
}

__global__ void concat3(const float* __restrict__ a, const float* __restrict__ b,
                        const float* __restrict__ c, float* __restrict__ dst)
{
    int i = blockIdx.x * 256 + threadIdx.x;
    if (i < D) { dst[i] = a[i]; dst[D + i] = b[i]; dst[2 * D + i] = c[i]; }
}

// ==================== fp16 mma flash attention (exp2, x4 ldsm, mask-skip) ===
#define QPAD 72
struct AttnSmem {
    __half Qh[128][QPAD];
    __half Kh[2][64][QPAD];
    __half Vh[2][64][QPAD];
};

__global__ __launch_bounds__(256, 2) void attn_mma(
    const __half* __restrict__ qg, const __half* __restrict__ kg,
    const __half* __restrict__ vg, __half* __restrict__ ctx, int ld)
{
    extern __shared__ char smem_raw[];
    AttnSmem& sm = *reinterpret_cast<AttnSmem*>(smem_raw);

    const int tid  = threadIdx.x;
    const int lane = tid & 31;
    const int w    = tid >> 5;
    const int g    = lane >> 2;
    const int t    = lane & 3;

    const int qt = (int)gridDim.x - 1 - (int)blockIdx.x;
    const int h  = blockIdx.y;
    const int b  = blockIdx.z;
    const size_t q0 = (size_t)b * SEQ + qt * 128;
    const int hcol = h * HD;
    const float SC = 0.125f * 1.44269504088896340736f;

    #pragma unroll
    for (int l = 0; l < 4; l++) {
        int f = tid + l * 256;
        int r = f >> 3, c = (f & 7) * 8;
        cp16(smem_u32(&sm.Qh[r][c]), qg + (q0 + r) * ld + hcol + c);
    }

    auto load_kv = [&](int st, int kt) {
        const size_t kr0 = (size_t)b * SEQ + kt * 64;
        #pragma unroll
        for (int l = 0; l < 2; l++) {
            int f = tid + l * 256;
            int r = f >> 3, c = (f & 7) * 8;
            const size_t go = (kr0 + r) * ld + hcol + c;
            cp16(smem_u32(&sm.Kh[st][r][c]), kg + go);
            cp16(smem_u32(&sm.Vh[st][r][c]), vg + go);
        }
    };

    load_kv(0, 0);
    cp_commit();

    const int ktiles = qt * 2 + 2;
    const int qbase = qt * 128 + w * 16;

    // precomputed x4-ldsm lane coords
    const int krow_lo = (lane & 7) + ((lane >> 4) & 1) * 8;  // key-block pair offset
    const int kcol8   = ((lane >> 3) & 1) * 8;
    const int vrow    = lane & 15;
    const int vcol8   = ((lane >> 4) & 1) * 8;

    unsigned qf[4][4];
    float m[2] = {-1e30f, -1e30f};
    float lsum[2] = {0.f, 0.f};
    float acc[8][4];
    #pragma unroll
    for (int nf = 0; nf < 8; nf++)
        #pragma unroll
        for (int i = 0; i < 4; i++) acc[nf][i] = 0.f;

    for (int kt = 0; kt < ktiles; kt++) {
        const int st = kt & 1;
        if (kt + 1 < ktiles) { load_kv(st ^ 1, kt + 1); cp_commit(); cp_wait<1>(); }
        else cp_wait<0>();
        __syncthreads();

        if (kt == 0) {
            #pragma unroll
            for (int kf = 0; kf < 4; kf++) {
                int r = w * 16 + (lane & 15);
                int c = kf * 16 + (lane >> 4) * 8;
                ldsm_x4(qf[kf], smem_u32(&sm.Qh[r][c]));
            }
        }

        float s[8][4];
        #pragma unroll
        for (int nf = 0; nf < 8; nf++)
            #pragma unroll
            for (int i = 0; i < 4; i++) s[nf][i] = 0.f;

        // ---- S = Q K^T : x4 ldsm loads two key-blocks per instruction ----
        #pragma unroll
        for (int nf2 = 0; nf2 < 4; nf2++) {
            #pragma unroll
            for (int kf = 0; kf < 4; kf++) {
                unsigned kb[4];
                int kr = nf2 * 16 + krow_lo;
                int kc = kf * 16 + kcol8;
                ldsm_x4(kb, smem_u32(&sm.Kh[st][kr][kc]));
                mma_f16(s[2*nf2],     qf[kf], kb);
                mma_f16(s[2*nf2 + 1], qf[kf], kb + 2);
            }
        }

        // ---- scale (+ mask only on diagonal-crossing tiles) ----
        const int kbase = kt * 64;
        if (kbase + 63 > qbase) {
            #pragma unroll
            for (int nf = 0; nf < 8; nf++) {
                #pragma unroll
                for (int i = 0; i < 4; i++) {
                    int key = kbase + nf * 8 + 2 * t + (i & 1);
                    int qry = qbase + g + (i >> 1) * 8;
                    float sv = s[nf][i] * SC;
                    s[nf][i] = (key > qry) ? -1e30f : sv;
                }
            }
        } else {
            #pragma unroll
            for (int nf = 0; nf < 8; nf++) {
                #pragma unroll
                for (int i = 0; i < 4; i++) s[nf][i] *= SC;
            }
        }

        // ---- online softmax (base-2) ----
        float cfac[2];
        #pragma unroll
        for (int r = 0; r < 2; r++) {
            float vmax = -1e30f;
            #pragma unroll
            for (int nf = 0; nf < 8; nf++) {
                vmax = fmaxf(vmax, s[nf][2 * r]);
                vmax = fmaxf(vmax, s[nf][2 * r + 1]);
            }
            vmax = fmaxf(vmax, __shfl_xor_sync(0xffffffffu, vmax, 1));
            vmax = fmaxf(vmax, __shfl_xor_sync(0xffffffffu, vmax, 2));
            float mn = fmaxf(m[r], vmax);
            cfac[r] = exp2f(m[r] - mn);
            m[r] = mn;
            float rowsum = 0.f;
            #pragma unroll
            for (int nf = 0; nf < 8; nf++) {
                float p0 = exp2f(s[nf][2 * r]     - mn);
                float p1 = exp2f(s[nf][2 * r + 1] - mn);
                s[nf][2 * r]     = p0;
                s[nf][2 * r + 1] = p1;
                rowsum += p0 + p1;
            }
            rowsum += __shfl_xor_sync(0xffffffffu, rowsum, 1);
            rowsum += __shfl_xor_sync(0xffffffffu, rowsum, 2);
            lsum[r] = lsum[r] * cfac[r] + rowsum;
        }
        #pragma unroll
        for (int nf = 0; nf < 8; nf++) {
            acc[nf][0] *= cfac[0]; acc[nf][1] *= cfac[0];
            acc[nf][2] *= cfac[1]; acc[nf][3] *= cfac[1];
        }

        // ---- pack P to fp16 A-fragments ----
        unsigned ph[4][4];
        #pragma unroll
        for (int kf = 0; kf < 4; kf++) {
            #pragma unroll
            for (int half = 0; half < 2; half++) {
                #pragma unroll
                for (int sub = 0; sub < 2; sub++) {
                    int nf = 2 * kf + sub;
                    ph[kf][sub * 2 + half] = pack_h2(s[nf][2 * half], s[nf][2 * half + 1]);
                }
            }
        }

        // ---- acc += P V : x4t ldsm loads two dim-blocks per instruction ----
        #pragma unroll
        for (int nf2 = 0; nf2 < 4; nf2++) {
            #pragma unroll
            for (int kf = 0; kf < 4; kf++) {
                unsigned vb[4];
                int vr = kf * 16 + vrow;
                int vc = nf2 * 16 + vcol8;
                ldsm_x4t(vb, smem_u32(&sm.Vh[st][vr][vc]));
                mma_f16(acc[2*nf2],     ph[kf], vb);
                mma_f16(acc[2*nf2 + 1], ph[kf], vb + 2);
            }
        }
        __syncthreads();
    }

    const float inv0 = 1.f / lsum[0];
    const float inv1 = 1.f / lsum[1];
    #pragma unroll
    for (int nf = 0; nf < 8; nf++) {
        int col = hcol + nf * 8 + 2 * t;
        size_t row0 = q0 + w * 16 + g;
        *(__half2*)(ctx + row0 * D + col)       = __floats2half2_rn(acc[nf][0] * inv0, acc[nf][1] * inv0);
        *(__half2*)(ctx + (row0 + 8) * D + col) = __floats2half2_rn(acc[nf][2] * inv1, acc[nf][3] * inv1);
    }
}

// ---------------- fused residual add + LayerNorm (float4 I/O) ---------------
template <int WB>
__global__ __launch_bounds__(256) void add_ln(
    const float* __restrict__ Ain, const float* __restrict__ Bin,
    const float* __restrict__ g, const float* __restrict__ be,
    float* __restrict__ out, __half* __restrict__ oh)
{
    const int row = blockIdx.x;
    const int tid = threadIdx.x;
    const float* a = Ain + (size_t)row * D;
    const float* b = Bin + (size_t)row * D;

    float4 va = *(const float4*)(a + tid * 4);
    float4 vb = *(const float4*)(b + tid * 4);
    float v0 = va.x + vb.x, v1 = va.y + vb.y, v2 = va.z + vb.z, v3 = va.w + vb.w;

    float s  = v0 + v1 + v2 + v3;
    float s2 = v0*v0 + v1*v1 + v2*v2 + v3*v3;
    #pragma unroll
    for (int off = 16; off > 0; off >>= 1) {
        s  += __shfl_xor_sync(0xffffffffu, s,  off);
        s2 += __shfl_xor_sync(0xffffffffu, s2, off);
    }
    __shared__ float sh[2][8];
    if ((tid & 31) == 0) { sh[0][tid >> 5] = s; sh[1][tid >> 5] = s2; }
    __syncthreads();
    float ts = 0.f, t2 = 0.f;
    #pragma unroll
    for (int w = 0; w < 8; w++) { ts += sh[0][w]; t2 += sh[1][w]; }

    const float mu  = ts * (1.f / D);
    const float var = t2 * (1.f / D) - mu * mu;
    const float inv = rsqrtf(var + 1e-5f);

    float4 gg = *(const float4*)(g + tid * 4);
    float4 bb = *(const float4*)(be + tid * 4);
    float o0 = (v0 - mu) * inv * gg.x + bb.x;
    float o1 = (v1 - mu) * inv * gg.y + bb.y;
    float o2 = (v2 - mu) * inv * gg.z + bb.z;
    float o3 = (v3 - mu) * inv * gg.w + bb.w;

    float4 ov; ov.x = o0; ov.y = o1; ov.z = o2; ov.w = o3;
    *(float4*)(out + (size_t)row * D + tid * 4) = ov;
    if (WB) {
        *(__half2*)(oh + (size_t)row * D + tid * 4)     = __floats2half2_rn(o0, o1);
        *(__half2*)(oh + (size_t)row * D + tid * 4 + 2) = __floats2half2_rn(o2, o3);
    }
}

// ---------------- launch -----------------------------------------------------
extern "C" void kernel_launch(void* const* d_in, const int* in_sizes, int n_in,
                              void* d_out, int out_size)
{
    const float* x    = (const float*)d_in[0];
    const float* Wq   = (const float*)d_in[1];
    const float* bq   = (const float*)d_in[2];
    const float* Wk   = (const float*)d_in[3];
    const float* bk   = (const float*)d_in[4];
    const float* Wv   = (const float*)d_in[5];
    const float* bv   = (const float*)d_in[6];
    const float* Wo   = (const float*)d_in[7];
    const float* bo   = (const float*)d_in[8];
    const float* ln1g = (const float*)d_in[9];
    const float* ln1b = (const float*)d_in[10];
    const float* W1   = (const float*)d_in[11];
    const float* b1   = (const float*)d_in[12];
    const float* W2   = (const float*)d_in[13];
    const float* b2   = (const float*)d_in[14];
    const float* ln2g = (const float*)d_in[15];
    const float* ln2b = (const float*)d_in[16];
    float* out = (float*)d_out;

    float *attnres, *h, *ff2, *bqkv;
    cudaGetSymbolAddress((void**)&attnres, g_attnres);
    cudaGetSymbolAddress((void**)&h,    g_h);
    cudaGetSymbolAddress((void**)&ff2,  g_ff2);
    cudaGetSymbolAddress((void**)&bqkv, g_bqkv);

    __half *x16,*qkv16,*ctx16,*h16,*f116,*wqkv16,*wo16,*w116,*w216;
    cudaGetSymbolAddress((void**)&x16,   g_x16);
    cudaGetSymbolAddress((void**)&qkv16, g_qkv16);
    cudaGetSymbolAddress((void**)&ctx16, g_ctx16);
    cudaGetSymbolAddress((void**)&h16,   g_h16);
    cudaGetSymbolAddress((void**)&f116,  g_f116);
    cudaGetSymbolAddress((void**)&wqkv16,g_wqkv16);
    cudaGetSymbolAddress((void**)&wo16,  g_wo16);
    cudaGetSymbolAddress((void**)&w116,  g_w116);
    cudaGetSymbolAddress((void**)&w216,  g_w216);

    static int attr_set = 0;
    if (!attr_set) {
        cudaFuncSetAttribute(gemm_f16<0>, cudaFuncAttributeMaxDynamicSharedMemorySize, (int)sizeof(GSmem));
        cudaFuncSetAttribute(gemm_f16<1>, cudaFuncAttributeMaxDynamicSharedMemorySize, (int)sizeof(GSmem));
        cudaFuncSetAttribute(gemm_f16<2>, cudaFuncAttributeMaxDynamicSharedMemorySize, (int)sizeof(GSmem));
        cudaFuncSetAttribute(attn_mma, cudaFuncAttributeMaxDynamicSharedMemorySize, (int)sizeof(AttnSmem));
        attr_set = 1;
    }
    const int SG = (int)sizeof(GSmem);
    const int SA = (int)sizeof(AttnSmem);

    // ---- conversions ----
    concat3<<<(D + 255)/256, 256>>>(bq, bk, bv, bqkv);
    convert_all<<<32768, 256>>>(x, Wq, Wk, Wv, Wo, W1, W2,
                                x16, wqkv16, wo16, w116, w216);

    // ---- merged QKV projection (fp16 out) ----
    dim3 gQKV(D3 / 128, MTOK / 128);
    gemm_f16<2><<<gQKV, 256, SG>>>(x16, wqkv16, bqkv, nullptr, qkv16, MTOK, D3, D);

    // ---- flash attention (fp16) ----
    dim3 gAttn(SEQ / 128, NH, BATCH);
    attn_mma<<<gAttn, 256, SA>>>(qkv16, qkv16 + D, qkv16 + 2*D, ctx16, D3);

    // ---- O projection ----
    dim3 gO(D / 128, MTOK / 128);
    gemm_f16<0><<<gO, 256, SG>>>(ctx16, wo16, bo, attnres, nullptr, MTOK, D, D);

    // ---- LN1 ----
    add_ln<1><<<MTOK, 256>>>(attnres, x, ln1g, ln1b, h, h16);

    // ---- FFN ----
    dim3 gFF1(FF / 128, MTOK / 128);
    gemm_f16<1><<<gFF1, 256, SG>>>(h16, w116, b1, nullptr, f116, MTOK, FF, D);

    dim3 gFF2(D / 128, MTOK / 128);
    gemm_f16<0><<<gFF2, 256, SG>>>(f116, w216, b2, ff2, nullptr, MTOK, D, FF);

    // ---- LN2 ----
    add_ln<0><<<MTOK, 256>>>(ff2, h, ln2g, ln2b, out, nullptr);
}